// round 8
// baseline (speedup 1.0000x reference)
#include <cuda_runtime.h>
#include <cuda_bf16.h>
#include <cstdint>

#define BB 4
#define LL 2048
#define EE 1024
#define HH 16
#define DD 64

// ---------------- scratch ----------------------------------------------------
__device__ float d_qg_buf[(size_t)BB * LL * HH * 2 * DD];  // (b,l,h,2D): q | gate
__device__ float d_k_buf [(size_t)BB * LL * HH * DD];      // (b,l,h,D)
__device__ float d_v_buf [(size_t)BB * LL * HH * DD];      // (b,l,h,D)
__device__ float d_ao_buf[(size_t)BB * LL * HH * DD];      // gated attn out
// pre-rounded (tf32-bit) copies of GEMM inputs
__device__ float d_h_tf [(size_t)BB * LL * EE];
__device__ float d_wq_tf[(size_t)EE * 2 * HH * DD];
__device__ float d_wk_tf[(size_t)EE * HH * DD];
__device__ float d_wv_tf[(size_t)EE * HH * DD];
__device__ float d_wo_tf[(size_t)HH * DD * EE];

// ---------------- helpers ----------------------------------------------------
__device__ __forceinline__ uint32_t f2tf(float x) {
    uint32_t r;
    asm("cvt.rna.tf32.f32 %0, %1;" : "=r"(r) : "f"(x));
    return r;
}
__device__ __forceinline__ float tfround(float x) {
    return __uint_as_float(f2tf(x));
}

__device__ __forceinline__ void mma_tf32(float* d,
    uint32_t a0, uint32_t a1, uint32_t a2, uint32_t a3,
    uint32_t b0, uint32_t b1)
{
    asm("mma.sync.aligned.m16n8k8.row.col.f32.tf32.tf32.f32 "
        "{%0,%1,%2,%3}, {%4,%5,%6,%7}, {%8,%9}, {%0,%1,%2,%3};"
        : "+f"(d[0]), "+f"(d[1]), "+f"(d[2]), "+f"(d[3])
        : "r"(a0), "r"(a1), "r"(a2), "r"(a3), "r"(b0), "r"(b1));
}

__device__ __forceinline__ uint32_t smem_u32(const void* p) {
    uint32_t a;
    asm("{ .reg .u64 t; cvta.to.shared.u64 t, %1; cvt.u32.u64 %0, t; }" : "=r"(a) : "l"(p));
    return a;
}

#define CP16(dst, src) \
    asm volatile("cp.async.cg.shared.global [%0], [%1], 16;" :: "r"(dst), "l"(src))
#define CP_COMMIT() asm volatile("cp.async.commit_group;")
#define CP_WAIT2()  asm volatile("cp.async.wait_group 2;" ::: "memory")
#define CP_WAIT0()  asm volatile("cp.async.wait_group 0;" ::: "memory")

// ---------------- tf32 rounding pre-pass -------------------------------------
__global__ __launch_bounds__(256) void cvt_tf32_kernel(
    const float4* __restrict__ src, float4* __restrict__ dst, int n4)
{
    int i = blockIdx.x * blockDim.x + threadIdx.x;
    if (i < n4) {
        float4 v = src[i];
        dst[i] = make_float4(tfround(v.x), tfround(v.y), tfround(v.z), tfround(v.w));
    }
}

// ---------------- tf32 GEMM: C[M,N] = A[M,K] @ B[K,N] ------------------------
// Inputs are pre-rounded tf32 bit patterns: NO per-load fixup needed.
// 256 threads, block tile 128x128, BK=32, 3-stage cp.async pipeline.
#define ASTR 36
#define BSTR 136
#define STAGE_U32 (128 * ASTR + 32 * BSTR)        // 8960 u32 = 35840 B
#define GEMM_SMEM_BYTES (3 * STAGE_U32 * 4)       // 107520 B

template <bool ROUND_OUT>
__global__ __launch_bounds__(256, 2) void tf32_gemm(
    const float* __restrict__ A, const float* __restrict__ Bm,
    float* __restrict__ C, int M, int N, int K)
{
    extern __shared__ uint32_t sh[];
    const uint32_t sbase = smem_u32(sh);

    const int tid = threadIdx.x;
    const int lane = tid & 31;
    const int w = tid >> 5;
    const int g = lane >> 2;
    const int t = lane & 3;
    const int wm = w & 3;
    const int wn = w >> 2;
    const int rowBase = blockIdx.y * 128;
    const int colBase = blockIdx.x * 128;

    const int ar = tid >> 3, as_ = tid & 7;
    const int br = tid >> 5, bs_ = tid & 31;

    const int nch = K / 32;

    auto issue = [&](int c) {
        if (c < nch) {
            const uint32_t st = sbase + (c % 3) * (STAGE_U32 * 4);
            const int k0 = c * 32;
#pragma unroll
            for (int i = 0; i < 4; i++) {
                int r = ar + i * 32;
                CP16(st + r * (ASTR * 4) + as_ * 16,
                     &A[(size_t)(rowBase + r) * K + k0 + as_ * 4]);
            }
            const uint32_t bst = st + 128 * ASTR * 4;
#pragma unroll
            for (int i = 0; i < 4; i++) {
                int r = br + i * 8;
                CP16(bst + r * (BSTR * 4) + bs_ * 16,
                     &Bm[(size_t)(k0 + r) * N + colBase + bs_ * 4]);
            }
        }
        CP_COMMIT();
    };

    float acc[2][8][4];
#pragma unroll
    for (int mt = 0; mt < 2; mt++)
#pragma unroll
        for (int nt = 0; nt < 8; nt++)
#pragma unroll
            for (int j = 0; j < 4; j++) acc[mt][nt][j] = 0.f;

    issue(0); issue(1); issue(2);

    for (int c = 0; c < nch; c++) {
        CP_WAIT2();
        __syncthreads();
        const uint32_t* Ac = sh + (c % 3) * STAGE_U32;
        const uint32_t* Bc = Ac + 128 * ASTR;

#pragma unroll
        for (int kk = 0; kk < 4; kk++) {
            const int k = kk * 8;
            uint32_t a[2][4];
#pragma unroll
            for (int mt = 0; mt < 2; mt++) {
                int r = wm * 32 + mt * 16 + g;
                a[mt][0] = Ac[r * ASTR + k + t];
                a[mt][1] = Ac[(r + 8) * ASTR + k + t];
                a[mt][2] = Ac[r * ASTR + k + t + 4];
                a[mt][3] = Ac[(r + 8) * ASTR + k + t + 4];
            }
            uint32_t b[8][2];
#pragma unroll
            for (int nt = 0; nt < 8; nt++) {
                int cn = wn * 64 + nt * 8 + g;
                b[nt][0] = Bc[(k + t) * BSTR + cn];
                b[nt][1] = Bc[(k + t + 4) * BSTR + cn];
            }
#pragma unroll
            for (int mt = 0; mt < 2; mt++)
#pragma unroll
                for (int nt = 0; nt < 8; nt++)
                    mma_tf32(acc[mt][nt], a[mt][0], a[mt][1], a[mt][2], a[mt][3],
                             b[nt][0], b[nt][1]);
        }
        __syncthreads();
        issue(c + 3);
    }

#pragma unroll
    for (int mt = 0; mt < 2; mt++) {
        int row = rowBase + wm * 32 + mt * 16 + g;
#pragma unroll
        for (int nt = 0; nt < 8; nt++) {
            int col = colBase + wn * 64 + nt * 8 + 2 * t;
            float v0 = acc[mt][nt][0], v1 = acc[mt][nt][1];
            float v2 = acc[mt][nt][2], v3 = acc[mt][nt][3];
            if (ROUND_OUT) {
                v0 = tfround(v0); v1 = tfround(v1);
                v2 = tfround(v2); v3 = tfround(v3);
            }
            *(float2*)&C[(size_t)row * N + col] = make_float2(v0, v1);
            *(float2*)&C[(size_t)(row + 8) * N + col] = make_float2(v2, v3);
        }
    }
}

// ---------------- RMSNorm + partial RoPE (writes tf32-rounded q/k) -----------
__global__ __launch_bounds__(256) void norm_rope_kernel(
    const float* __restrict__ cosb, const float* __restrict__ sinb,
    const float* __restrict__ qw, const float* __restrict__ kw)
{
    int gw = (blockIdx.x * blockDim.x + threadIdx.x) >> 5;
    int lane = threadIdx.x & 31;
    int which = gw & 1;
    int row = gw >> 1;
    if (row >= BB * LL * HH) return;
    int h = row % HH;
    int bl = row / HH;

    float* ptr;
    const float* w;
    if (which == 0) { ptr = d_qg_buf + ((size_t)bl * HH + h) * (2 * DD); w = qw; }
    else            { ptr = d_k_buf  + ((size_t)bl * HH + h) * DD;       w = kw; }

    float x0 = ptr[lane];
    float x1 = ptr[lane + 32];
    float ss = x0 * x0 + x1 * x1;
#pragma unroll
    for (int o = 16; o; o >>= 1) ss += __shfl_xor_sync(0xffffffffu, ss, o);
    float r = rsqrtf(ss * (1.0f / 64.0f) + 1e-6f);
    x0 = x0 * r * w[lane];
    x1 = x1 * r * w[lane + 32];

    float c0 = 1.f, s0 = 0.f, c1 = 1.f, s1 = 0.f;
    if (lane < 24) {
        const float* cp = cosb + (size_t)bl * DD;
        const float* sp = sinb + (size_t)bl * DD;
        c0 = cp[lane];      s0 = sp[lane];
        c1 = cp[lane + 32]; s1 = sp[lane + 32];
    }
    float r0 = x0 * c0 - x1 * s0;
    float r1 = x1 * c1 + x0 * s1;
    if (which == 0) { r0 *= 0.125f; r1 *= 0.125f; }   // fold 1/sqrt(D) into q
    ptr[lane]      = tfround(r0);
    ptr[lane + 32] = tfround(r1);
}

// ---------------- tf32 flash attention (no-max softmax) + sigmoid gate -------
// All mma operands (Q/K/V) arrive pre-rounded: staging is pure copies.
// PAD=72: all smem patterns bank-conflict-free. Mask cp.async-staged into Ps.
#define PAD 72
#define ATTN_SMEM_U32 (128 * PAD + 64 * PAD + 64 * PAD + 128 * PAD)  // 27648 u32

__global__ __launch_bounds__(256, 2) void attn_tf32_kernel(const float* __restrict__ mask)
{
    extern __shared__ uint32_t sh[];
    uint32_t* Qs = sh;                    // [128][PAD]
    uint32_t* Ks = sh + 128 * PAD;        // [64][PAD]
    uint32_t* Vs = sh + 192 * PAD;        // [64][PAD]
    uint32_t* Ps = sh + 256 * PAD;        // [128][PAD]  (mask tile, then P)

    const uint32_t ps_u32 = smem_u32(Ps);

    const int tid = threadIdx.x;
    const int lane = tid & 31;
    const int w = tid >> 5;
    const int g = lane >> 2;
    const int t = lane & 3;
    const int h = blockIdx.x;
    const int q0 = blockIdx.y * 128;
    const int b = blockIdx.z;

    // stage Q tile (pre-rounded & pre-scaled: plain copy)
#pragma unroll
    for (int i = 0; i < 8; i++) {
        int lin = tid + 256 * i;
        int row = lin >> 4, c4 = lin & 15;
        uint4 u = *(const uint4*)&d_qg_buf[(((size_t)(b * LL + q0 + row)) * HH + h) * 128 + c4 * 4];
        *(uint4*)&Qs[row * PAD + c4 * 4] = u;
    }

    float o[4][2][4];
#pragma unroll
    for (int mt = 0; mt < 4; mt++)
#pragma unroll
        for (int nt = 0; nt < 2; nt++)
#pragma unroll
            for (int j = 0; j < 4; j++) o[mt][nt][j] = 0.f;

    float l_run[2] = {0.f, 0.f};
    const int ldr = tid >> 4, ldc = tid & 15;   // K/V load: 16 rows x 16 segs
    const int mrow = tid >> 4;                  // mask rows 0..15 step 16
    const int mseg = tid & 15;                  // mask float4 seg

    // prefetch K/V tile 0 into registers (raw bits; already rounded)
    uint4 kr[4], vr[4];
#pragma unroll
    for (int i = 0; i < 4; i++) {
        size_t base = (((size_t)(b * LL + ldr + i * 16)) * HH + h) * 64 + ldc * 4;
        kr[i] = *(const uint4*)&d_k_buf[base];
        vr[i] = *(const uint4*)&d_v_buf[base];
    }

    for (int k0 = 0; k0 < LL; k0 += 64) {
        __syncthreads();   // prior tile's PV-mma / P reads complete
#pragma unroll
        for (int i = 0; i < 4; i++) {
            int row = ldr + i * 16;
            *(uint4*)&Ks[row * PAD + ldc * 4] = kr[i];
            *(uint4*)&Vs[row * PAD + ldc * 4] = vr[i];
        }
        if (k0 + 64 < LL) {
#pragma unroll
            for (int i = 0; i < 4; i++) {
                size_t base = (((size_t)(b * LL + k0 + 64 + ldr + i * 16)) * HH + h) * 64 + ldc * 4;
                kr[i] = *(const uint4*)&d_k_buf[base];
                vr[i] = *(const uint4*)&d_v_buf[base];
            }
        }
        // async-stage mask tile [128 q][64 k] into Ps (hidden under S-mma)
#pragma unroll
        for (int i = 0; i < 8; i++) {
            int r = mrow + i * 16;
            CP16(ps_u32 + r * (PAD * 4) + mseg * 16,
                 &mask[((size_t)(b * LL + q0 + r)) * LL + k0 + mseg * 4]);
        }
        CP_COMMIT();
        __syncthreads();   // K/V visible

        // S = Q @ K^T
        float s[8][4];
#pragma unroll
        for (int nt = 0; nt < 8; nt++)
#pragma unroll
            for (int j = 0; j < 4; j++) s[nt][j] = 0.f;

#pragma unroll
        for (int ks = 0; ks < 8; ks++) {
            const int k = ks * 8;
            int r = w * 16 + g;
            uint32_t a0 = Qs[r * PAD + k + t];
            uint32_t a1 = Qs[(r + 8) * PAD + k + t];
            uint32_t a2 = Qs[r * PAD + k + t + 4];
            uint32_t a3 = Qs[(r + 8) * PAD + k + t + 4];
#pragma unroll
            for (int nt = 0; nt < 8; nt++) {
                uint32_t b0 = Ks[(nt * 8 + g) * PAD + k + t];
                uint32_t b1 = Ks[(nt * 8 + g) * PAD + k + t + 4];
                mma_tf32(s[nt], a0, a1, a2, a3, b0, b1);
            }
        }

        CP_WAIT0();
        __syncthreads();   // mask tile visible

        // mask + exp + rowsum (no max subtraction; scores bounded by rmsnorm)
        {
            const uint32_t* mp0 = Ps + (w * 16 + g) * PAD;
            const uint32_t* mp1 = mp0 + 8 * PAD;
            float sum[2] = {0.f, 0.f};
#pragma unroll
            for (int nt = 0; nt < 8; nt++) {
                float2 m0 = *(const float2*)&mp0[nt * 8 + 2 * t];
                float2 m1 = *(const float2*)&mp1[nt * 8 + 2 * t];
                s[nt][0] = __expf(s[nt][0] + m0.x);
                s[nt][1] = __expf(s[nt][1] + m0.y);
                s[nt][2] = __expf(s[nt][2] + m1.x);
                s[nt][3] = __expf(s[nt][3] + m1.y);
                sum[0] += s[nt][0] + s[nt][1];
                sum[1] += s[nt][2] + s[nt][3];
            }
#pragma unroll
            for (int i = 0; i < 2; i++) {
                sum[i] += __shfl_xor_sync(0xffffffffu, sum[i], 1);
                sum[i] += __shfl_xor_sync(0xffffffffu, sum[i], 2);
                l_run[i] += sum[i];
            }
        }

        // store P (tf32) over the mask slots this thread just consumed
        {
            int r = w * 16 + g;
#pragma unroll
            for (int nt = 0; nt < 8; nt++) {
                *(uint2*)&Ps[r * PAD + nt * 8 + 2 * t] =
                    make_uint2(f2tf(s[nt][0]), f2tf(s[nt][1]));
                *(uint2*)&Ps[(r + 8) * PAD + nt * 8 + 2 * t] =
                    make_uint2(f2tf(s[nt][2]), f2tf(s[nt][3]));
            }
        }
        __syncwarp();      // P rows are warp-private

        // O^T += V^T @ P^T
#pragma unroll
        for (int ks = 0; ks < 8; ks++) {
            const int k = ks * 8;
            uint32_t bfr[2][2];
#pragma unroll
            for (int nt = 0; nt < 2; nt++) {
                int pr = w * 16 + nt * 8 + g;
                bfr[nt][0] = Ps[pr * PAD + k + t];
                bfr[nt][1] = Ps[pr * PAD + k + t + 4];
            }
#pragma unroll
            for (int mt = 0; mt < 4; mt++) {
                int dcol = mt * 16 + g;
                uint32_t a0 = Vs[(k + t) * PAD + dcol];
                uint32_t a1 = Vs[(k + t) * PAD + dcol + 8];
                uint32_t a2 = Vs[(k + t + 4) * PAD + dcol];
                uint32_t a3 = Vs[(k + t + 4) * PAD + dcol + 8];
#pragma unroll
                for (int nt = 0; nt < 2; nt++)
                    mma_tf32(o[mt][nt], a0, a1, a2, a3, bfr[nt][0], bfr[nt][1]);
            }
        }
    }

    // epilogue: normalize, gate, round for out-proj, store
    float inv[2][2];
#pragma unroll
    for (int nt = 0; nt < 2; nt++)
#pragma unroll
        for (int j = 0; j < 2; j++)
            inv[nt][j] = 1.0f / __shfl_sync(0xffffffffu, l_run[nt], (2 * t + j) * 4);

#pragma unroll
    for (int nt = 0; nt < 2; nt++)
#pragma unroll
        for (int j = 0; j < 2; j++) {
            int q = q0 + w * 16 + nt * 8 + 2 * t + j;
            size_t gbase = (((size_t)(b * LL + q)) * HH + h) * 128 + 64;
            size_t obase = (((size_t)(b * LL + q)) * HH + h) * 64;
#pragma unroll
            for (int mt = 0; mt < 4; mt++) {
                int d0 = mt * 16 + g;
                float g0 = d_qg_buf[gbase + d0];
                float g1 = d_qg_buf[gbase + d0 + 8];
                float v0 = o[mt][nt][j] * inv[nt][j];
                float v1 = o[mt][nt][j + 2] * inv[nt][j];
                d_ao_buf[obase + d0]     = tfround(v0 * (1.0f / (1.0f + __expf(-g0))));
                d_ao_buf[obase + d0 + 8] = tfround(v1 * (1.0f / (1.0f + __expf(-g1))));
            }
        }
}

// ---------------------------------------------------------------------------
extern "C" void kernel_launch(void* const* d_in, const int* in_sizes, int n_in,
                              void* d_out, int out_size)
{
    (void)in_sizes; (void)n_in; (void)out_size;
    const float* h    = (const float*)d_in[0];
    const float* cosb = (const float*)d_in[1];
    const float* sinb = (const float*)d_in[2];
    const float* mask = (const float*)d_in[3];
    const float* wq   = (const float*)d_in[4];
    const float* wk   = (const float*)d_in[5];
    const float* wv   = (const float*)d_in[6];
    const float* wo   = (const float*)d_in[7];
    const float* qnw  = (const float*)d_in[8];
    const float* knw  = (const float*)d_in[9];
    float* out = (float*)d_out;

    float *qg, *kp, *vp, *ao, *htf, *wqtf, *wktf, *wvtf, *wotf;
    cudaGetSymbolAddress((void**)&qg, d_qg_buf);
    cudaGetSymbolAddress((void**)&kp, d_k_buf);
    cudaGetSymbolAddress((void**)&vp, d_v_buf);
    cudaGetSymbolAddress((void**)&ao, d_ao_buf);
    cudaGetSymbolAddress((void**)&htf, d_h_tf);
    cudaGetSymbolAddress((void**)&wqtf, d_wq_tf);
    cudaGetSymbolAddress((void**)&wktf, d_wk_tf);
    cudaGetSymbolAddress((void**)&wvtf, d_wv_tf);
    cudaGetSymbolAddress((void**)&wotf, d_wo_tf);

    const int M = BB * LL;   // 8192

    // pre-round GEMM inputs to tf32 bit patterns
    auto cvt = [](const float* s, float* d, size_t n) {
        int n4 = (int)(n / 4);
        cvt_tf32_kernel<<<(n4 + 255) / 256, 256>>>((const float4*)s, (float4*)d, n4);
    };
    cvt(h,  htf,  (size_t)M * EE);
    cvt(wq, wqtf, (size_t)EE * 2 * HH * DD);
    cvt(wk, wktf, (size_t)EE * HH * DD);
    cvt(wv, wvtf, (size_t)EE * HH * DD);
    cvt(wo, wotf, (size_t)HH * DD * EE);

    cudaFuncSetAttribute(tf32_gemm<false>, cudaFuncAttributeMaxDynamicSharedMemorySize,
                         GEMM_SMEM_BYTES);
    cudaFuncSetAttribute(tf32_gemm<true>, cudaFuncAttributeMaxDynamicSharedMemorySize,
                         GEMM_SMEM_BYTES);

    // QKV projections (v output rounded for attention mma)
    tf32_gemm<false><<<dim3(16, 64), 256, GEMM_SMEM_BYTES>>>(htf, wqtf, qg, M, 2 * HH * DD, EE);
    tf32_gemm<false><<<dim3(8, 64), 256, GEMM_SMEM_BYTES>>>(htf, wktf, kp, M, HH * DD, EE);
    tf32_gemm<true ><<<dim3(8, 64), 256, GEMM_SMEM_BYTES>>>(htf, wvtf, vp, M, HH * DD, EE);

    // RMSNorm + partial RoPE (writes rounded q*0.125 and k)
    {
        int warps = BB * LL * HH * 2;
        int blocks = (warps * 32 + 255) / 256;
        norm_rope_kernel<<<blocks, 256>>>(cosb, sinb, qnw, knw);
    }

    // fused tf32 flash attention + gate (grid.x = h for mask L2 reuse)
    {
        int smem = ATTN_SMEM_U32 * 4;
        cudaFuncSetAttribute(attn_tf32_kernel, cudaFuncAttributeMaxDynamicSharedMemorySize, smem);
        attn_tf32_kernel<<<dim3(HH, LL / 128, BB), 256, smem>>>(mask);
    }

    // output projection (ao pre-rounded by attention epilogue)
    tf32_gemm<false><<<dim3(8, 64), 256, GEMM_SMEM_BYTES>>>(ao, wotf, out, M, EE, EE);
}

// round 10
// speedup vs baseline: 1.4690x; 1.4690x over previous
#include <cuda_runtime.h>
#include <cuda_fp16.h>
#include <cstdint>

#define BB 4
#define LL 2048
#define EE 1024
#define HH 16
#define DD 64

// ---------------- scratch ----------------------------------------------------
__device__ float d_qg_buf[(size_t)BB * LL * HH * 2 * DD];  // (b,l,h,2D): q | gate (f32)
__device__ float d_k_buf [(size_t)BB * LL * HH * DD];      // f32 k (pre-norm)
__device__ float d_v_buf [(size_t)BB * LL * HH * DD];      // f32 v
__device__ __half d_h16  [(size_t)BB * LL * EE];           // fp16 h
__device__ __half d_wq16t[(size_t)2 * HH * DD * EE];       // [N][K] fp16
__device__ __half d_wk16t[(size_t)HH * DD * EE];
__device__ __half d_wv16t[(size_t)HH * DD * EE];
__device__ __half d_wo16t[(size_t)EE * HH * DD];
__device__ __half d_q16  [(size_t)BB * LL * HH * DD];      // normed+rope q * 0.125
__device__ __half d_k16  [(size_t)BB * LL * HH * DD];      // normed+rope k
__device__ __half d_vt16 [(size_t)BB * HH * DD * LL];      // V^T per head: [b,h,d,l]
__device__ __half d_ao16 [(size_t)BB * LL * HH * DD];      // gated attn out fp16

// ---------------- helpers ----------------------------------------------------
__device__ __forceinline__ void mma_f16(float* d,
    uint32_t a0, uint32_t a1, uint32_t a2, uint32_t a3,
    uint32_t b0, uint32_t b1)
{
    asm("mma.sync.aligned.m16n8k16.row.col.f32.f16.f16.f32 "
        "{%0,%1,%2,%3}, {%4,%5,%6,%7}, {%8,%9}, {%0,%1,%2,%3};"
        : "+f"(d[0]), "+f"(d[1]), "+f"(d[2]), "+f"(d[3])
        : "r"(a0), "r"(a1), "r"(a2), "r"(a3), "r"(b0), "r"(b1));
}

__device__ __forceinline__ uint32_t smem_u32(const void* p) {
    uint32_t a;
    asm("{ .reg .u64 t; cvta.to.shared.u64 t, %1; cvt.u32.u64 %0, t; }" : "=r"(a) : "l"(p));
    return a;
}

__device__ __forceinline__ uint32_t pack2(float x, float y) {
    __half2 h = __floats2half2_rn(x, y);
    return *(uint32_t*)&h;
}

#define CP16(dst, src) \
    asm volatile("cp.async.cg.shared.global [%0], [%1], 16;" :: "r"(dst), "l"(src))
#define CP_COMMIT() asm volatile("cp.async.commit_group;")
#define CP_WAIT2()  asm volatile("cp.async.wait_group 2;" ::: "memory")
#define CP_WAIT0()  asm volatile("cp.async.wait_group 0;" ::: "memory")

// ---------------- f32 -> f16 elementwise (8 elems/thread) --------------------
__global__ __launch_bounds__(256) void cvt_h16_kernel(
    const float4* __restrict__ src, uint4* __restrict__ dst, int n8)
{
    int i = blockIdx.x * blockDim.x + threadIdx.x;
    if (i < n8) {
        float4 a = src[2 * i], b = src[2 * i + 1];
        dst[i] = make_uint4(pack2(a.x, a.y), pack2(a.z, a.w),
                            pack2(b.x, b.y), pack2(b.z, b.w));
    }
}

// ---------------- transpose + cvt: W [K][N] f32 -> Wt [N][K] f16 -------------
__global__ __launch_bounds__(256) void transpose_w_kernel(
    const float* __restrict__ in, __half* __restrict__ out, int K, int N)
{
    __shared__ float sm[32][33];
    int n0 = blockIdx.x * 32, k0 = blockIdx.y * 32;
    int tx = threadIdx.x, ty = threadIdx.y;
#pragma unroll
    for (int i = 0; i < 4; i++)
        sm[ty + i * 8][tx] = in[(size_t)(k0 + ty + i * 8) * N + n0 + tx];
    __syncthreads();
#pragma unroll
    for (int i = 0; i < 4; i++)
        out[(size_t)(n0 + ty + i * 8) * K + k0 + tx] = __float2half(sm[tx][ty + i * 8]);
}

// ---------------- per-head V transpose: v[b,l,h,d] f32 -> vt[b,h,d,l] f16 ----
__global__ __launch_bounds__(256) void vtrans_kernel()
{
    __shared__ float sm[32][33];
    int bh = blockIdx.z;                    // b*16 + h
    int b = bh >> 4, h = bh & 15;
    int d0 = blockIdx.y * 32, l0 = blockIdx.x * 32;
    int tx = threadIdx.x, ty = threadIdx.y;
#pragma unroll
    for (int i = 0; i < 4; i++)
        sm[ty + i * 8][tx] =
            d_v_buf[(((size_t)(b * LL + l0 + ty + i * 8)) * HH + h) * DD + d0 + tx];
    __syncthreads();
#pragma unroll
    for (int i = 0; i < 4; i++)
        d_vt16[((size_t)bh * DD + d0 + ty + i * 8) * LL + l0 + tx] =
            __float2half(sm[tx][ty + i * 8]);
}

// ---------------- fp16 GEMM: C[M,N] = A[M,K] @ Bt[N,K]^T ---------------------
// A,Bt fp16 row-major; C f32. 128x128 tile, BK=64, 3-stage cp.async.
// smem u32-stride 36 (=72 f16 = 144B rows): conflict-free fragments.
#define GSTR 36
#define GSTAGE_U32 (2 * 128 * GSTR)              // 9216 u32 = 36864 B
#define GEMM_SMEM_BYTES (3 * GSTAGE_U32 * 4)     // 110592 B

__global__ __launch_bounds__(256, 2) void h16_gemm(
    const __half* __restrict__ A, const __half* __restrict__ Bt,
    float* __restrict__ C, int M, int N, int K)
{
    extern __shared__ uint32_t sh[];
    const uint32_t sbase = smem_u32(sh);

    const int tid = threadIdx.x;
    const int lane = tid & 31;
    const int w = tid >> 5;
    const int g = lane >> 2;
    const int t = lane & 3;
    const int wm = w & 3;
    const int wn = w >> 2;
    const int rowBase = blockIdx.y * 128;
    const int colBase = blockIdx.x * 128;

    const int crow = tid >> 1;                // 0..127
    const int csb = (tid & 1) * 4;            // seg base (segs of 16B)

    const int nch = K / 64;

    auto issue = [&](int c) {
        if (c < nch) {
            const uint32_t st = sbase + (c % 3) * (GSTAGE_U32 * 4);
            const int k0 = c * 64;
#pragma unroll
            for (int i = 0; i < 4; i++)
                CP16(st + crow * 144 + (csb + i) * 16,
                     &A[(size_t)(rowBase + crow) * K + k0 + (csb + i) * 8]);
            const uint32_t bst = st + 128 * 144;
#pragma unroll
            for (int i = 0; i < 4; i++)
                CP16(bst + crow * 144 + (csb + i) * 16,
                     &Bt[(size_t)(colBase + crow) * K + k0 + (csb + i) * 8]);
        }
        CP_COMMIT();
    };

    float acc[2][8][4];
#pragma unroll
    for (int mt = 0; mt < 2; mt++)
#pragma unroll
        for (int nt = 0; nt < 8; nt++)
#pragma unroll
            for (int j = 0; j < 4; j++) acc[mt][nt][j] = 0.f;

    issue(0); issue(1); issue(2);

    for (int c = 0; c < nch; c++) {
        CP_WAIT2();
        __syncthreads();
        const uint32_t* Au = sh + (c % 3) * GSTAGE_U32;
        const uint32_t* Bu = Au + 128 * GSTR;

#pragma unroll
        for (int kk = 0; kk < 4; kk++) {
            uint32_t a[2][4];
#pragma unroll
            for (int mt = 0; mt < 2; mt++) {
                int r = wm * 32 + mt * 16 + g;
                a[mt][0] = Au[r * GSTR + kk * 8 + t];
                a[mt][1] = Au[(r + 8) * GSTR + kk * 8 + t];
                a[mt][2] = Au[r * GSTR + kk * 8 + t + 4];
                a[mt][3] = Au[(r + 8) * GSTR + kk * 8 + t + 4];
            }
            uint32_t b[8][2];
#pragma unroll
            for (int nt = 0; nt < 8; nt++) {
                int cn = wn * 64 + nt * 8 + g;
                b[nt][0] = Bu[cn * GSTR + kk * 8 + t];
                b[nt][1] = Bu[cn * GSTR + kk * 8 + t + 4];
            }
#pragma unroll
            for (int mt = 0; mt < 2; mt++)
#pragma unroll
                for (int nt = 0; nt < 8; nt++)
                    mma_f16(acc[mt][nt], a[mt][0], a[mt][1], a[mt][2], a[mt][3],
                            b[nt][0], b[nt][1]);
        }
        __syncthreads();
        issue(c + 3);
    }

#pragma unroll
    for (int mt = 0; mt < 2; mt++) {
        int row = rowBase + wm * 32 + mt * 16 + g;
#pragma unroll
        for (int nt = 0; nt < 8; nt++) {
            int col = colBase + wn * 64 + nt * 8 + 2 * t;
            *(float2*)&C[(size_t)row * N + col] = make_float2(acc[mt][nt][0], acc[mt][nt][1]);
            *(float2*)&C[(size_t)(row + 8) * N + col] = make_float2(acc[mt][nt][2], acc[mt][nt][3]);
        }
    }
}

// ---------------- RMSNorm + partial RoPE -> fp16 q/k -------------------------
__global__ __launch_bounds__(256) void norm_rope_kernel(
    const float* __restrict__ cosb, const float* __restrict__ sinb,
    const float* __restrict__ qw, const float* __restrict__ kw)
{
    int gw = (blockIdx.x * blockDim.x + threadIdx.x) >> 5;
    int lane = threadIdx.x & 31;
    int which = gw & 1;
    int row = gw >> 1;
    if (row >= BB * LL * HH) return;
    int h = row % HH;
    int bl = row / HH;

    const float* ptr;
    const float* w;
    if (which == 0) { ptr = d_qg_buf + ((size_t)bl * HH + h) * (2 * DD); w = qw; }
    else            { ptr = d_k_buf  + ((size_t)bl * HH + h) * DD;       w = kw; }

    float x0 = ptr[lane];
    float x1 = ptr[lane + 32];
    float ss = x0 * x0 + x1 * x1;
#pragma unroll
    for (int o = 16; o; o >>= 1) ss += __shfl_xor_sync(0xffffffffu, ss, o);
    float r = rsqrtf(ss * (1.0f / 64.0f) + 1e-6f);
    x0 = x0 * r * w[lane];
    x1 = x1 * r * w[lane + 32];

    float c0 = 1.f, s0 = 0.f, c1 = 1.f, s1 = 0.f;
    if (lane < 24) {
        const float* cp = cosb + (size_t)bl * DD;
        const float* sp = sinb + (size_t)bl * DD;
        c0 = cp[lane];      s0 = sp[lane];
        c1 = cp[lane + 32]; s1 = sp[lane + 32];
    }
    float r0 = x0 * c0 - x1 * s0;
    float r1 = x1 * c1 + x0 * s1;
    __half* dst;
    if (which == 0) { r0 *= 0.125f; r1 *= 0.125f; dst = d_q16 + ((size_t)bl * HH + h) * DD; }
    else            { dst = d_k16 + ((size_t)bl * HH + h) * DD; }
    dst[lane]      = __float2half(r0);
    dst[lane + 32] = __float2half(r1);
}

// ---------------- fp16 flash attention (register online softmax) + gate ------
// smem (u32): Qu[128*36] Ku[64*36] Vu[64*36] Pu[128*36] Ms(f32)[128*68]
#define AQ_OFF 0
#define AK_OFF (128 * 36)
#define AV_OFF (192 * 36)
#define AP_OFF (256 * 36)
#define AM_OFF (384 * 36)
#define ATTN_SMEM_U32 (384 * 36 + 128 * 68)   // 22528 u32 = 90112 B

__global__ __launch_bounds__(256, 2) void attn_f16_kernel(const float* __restrict__ mask)
{
    extern __shared__ uint32_t sh[];
    uint32_t* Qu = sh + AQ_OFF;
    uint32_t* Ku = sh + AK_OFF;
    uint32_t* Vu = sh + AV_OFF;
    uint32_t* Pu = sh + AP_OFF;
    float* Ms = (float*)(sh + AM_OFF);
    const uint32_t ms_base = smem_u32(Ms);

    const int tid = threadIdx.x;
    const int lane = tid & 31;
    const int w = tid >> 5;
    const int g = lane >> 2;
    const int t = lane & 3;
    const int h = blockIdx.x;
    const int q0 = blockIdx.y * 128;
    const int b = blockIdx.z;

    // stage Q tile (fp16, pre-scaled): 4 x uint4 per thread
    {
        int row = tid >> 1, sb = (tid & 1) * 4;
#pragma unroll
        for (int i = 0; i < 4; i++) {
            uint4 u = *(const uint4*)&d_q16[(((size_t)(b * LL + q0 + row)) * HH + h) * DD + (sb + i) * 8];
            *(uint4*)&Qu[row * 36 + (sb + i) * 4] = u;
        }
    }

    float o[4][2][4];
#pragma unroll
    for (int mt = 0; mt < 4; mt++)
#pragma unroll
        for (int nt = 0; nt < 2; nt++)
#pragma unroll
            for (int j = 0; j < 4; j++) o[mt][nt][j] = 0.f;

    float m_run[2] = {-1e30f, -1e30f};
    float l_run[2] = {0.f, 0.f};

    const int kvrow = tid >> 2;                 // 0..63
    const int kvsb = (tid & 3) * 2;             // seg base
    const int mrow = tid >> 4;                  // mask row base 0..15
    const int mseg = tid & 15;                  // mask seg 0..15

    // prefetch K / V^T tile 0
    uint4 kr[2], vr[2];
#pragma unroll
    for (int i = 0; i < 2; i++) {
        kr[i] = *(const uint4*)&d_k16[(((size_t)(b * LL + kvrow)) * HH + h) * DD + (kvsb + i) * 8];
        vr[i] = *(const uint4*)&d_vt16[(((size_t)(b * HH + h)) * DD + kvrow) * LL + 0 + (kvsb + i) * 8];
    }

    for (int k0 = 0; k0 < LL; k0 += 64) {
        __syncthreads();
#pragma unroll
        for (int i = 0; i < 2; i++) {
            *(uint4*)&Ku[kvrow * 36 + (kvsb + i) * 4] = kr[i];
            *(uint4*)&Vu[kvrow * 36 + (kvsb + i) * 4] = vr[i];
        }
        if (k0 + 64 < LL) {
#pragma unroll
            for (int i = 0; i < 2; i++) {
                kr[i] = *(const uint4*)&d_k16[(((size_t)(b * LL + k0 + 64 + kvrow)) * HH + h) * DD + (kvsb + i) * 8];
                vr[i] = *(const uint4*)&d_vt16[(((size_t)(b * HH + h)) * DD + kvrow) * LL + k0 + 64 + (kvsb + i) * 8];
            }
        }
        // async mask tile [128 q][64 k] f32 into Ms
#pragma unroll
        for (int i = 0; i < 8; i++) {
            int r = mrow + i * 16;
            CP16(ms_base + r * (68 * 4) + mseg * 16,
                 &mask[((size_t)(b * LL + q0 + r)) * LL + k0 + mseg * 4]);
        }
        CP_COMMIT();
        __syncthreads();

        // S = Q @ K^T  (fp16 mma, 4 k-steps over d)
        float s[8][4];
#pragma unroll
        for (int nt = 0; nt < 8; nt++)
#pragma unroll
            for (int j = 0; j < 4; j++) s[nt][j] = 0.f;

#pragma unroll
        for (int kk = 0; kk < 4; kk++) {
            int r = w * 16 + g;
            uint32_t a0 = Qu[r * 36 + kk * 8 + t];
            uint32_t a1 = Qu[(r + 8) * 36 + kk * 8 + t];
            uint32_t a2 = Qu[r * 36 + kk * 8 + t + 4];
            uint32_t a3 = Qu[(r + 8) * 36 + kk * 8 + t + 4];
#pragma unroll
            for (int nt = 0; nt < 8; nt++) {
                uint32_t b0 = Ku[(nt * 8 + g) * 36 + kk * 8 + t];
                uint32_t b1 = Ku[(nt * 8 + g) * 36 + kk * 8 + t + 4];
                mma_f16(s[nt], a0, a1, a2, a3, b0, b1);
            }
        }

        CP_WAIT0();
        __syncthreads();   // mask visible

        // add mask, online row-max, exp, rowsum, P->fp16
        {
            const float* mp0 = Ms + (w * 16 + g) * 68;
            const float* mp1 = mp0 + 8 * 68;
#pragma unroll
            for (int nt = 0; nt < 8; nt++) {
                float2 m0 = *(const float2*)&mp0[nt * 8 + 2 * t];
                float2 m1 = *(const float2*)&mp1[nt * 8 + 2 * t];
                s[nt][0] += m0.x; s[nt][1] += m0.y;
                s[nt][2] += m1.x; s[nt][3] += m1.y;
            }
            float mx[2] = {-1e30f, -1e30f};
#pragma unroll
            for (int nt = 0; nt < 8; nt++) {
                mx[0] = fmaxf(mx[0], fmaxf(s[nt][0], s[nt][1]));
                mx[1] = fmaxf(mx[1], fmaxf(s[nt][2], s[nt][3]));
            }
#pragma unroll
            for (int i = 0; i < 2; i++) {
                mx[i] = fmaxf(mx[i], __shfl_xor_sync(0xffffffffu, mx[i], 1));
                mx[i] = fmaxf(mx[i], __shfl_xor_sync(0xffffffffu, mx[i], 2));
            }
            float m_new[2], corr[2], sum[2] = {0.f, 0.f};
#pragma unroll
            for (int i = 0; i < 2; i++) {
                m_new[i] = fmaxf(m_run[i], mx[i]);
                corr[i] = __expf(m_run[i] - m_new[i]);
                m_run[i] = m_new[i];
            }
#pragma unroll
            for (int nt = 0; nt < 8; nt++) {
                s[nt][0] = __expf(s[nt][0] - m_new[0]);
                s[nt][1] = __expf(s[nt][1] - m_new[0]);
                s[nt][2] = __expf(s[nt][2] - m_new[1]);
                s[nt][3] = __expf(s[nt][3] - m_new[1]);
                sum[0] += s[nt][0] + s[nt][1];
                sum[1] += s[nt][2] + s[nt][3];
            }
#pragma unroll
            for (int i = 0; i < 2; i++) {
                sum[i] += __shfl_xor_sync(0xffffffffu, sum[i], 1);
                sum[i] += __shfl_xor_sync(0xffffffffu, sum[i], 2);
                l_run[i] = l_run[i] * corr[i] + sum[i];
            }
            // store P fp16 (rows warp-private)
            int r = w * 16 + g;
#pragma unroll
            for (int nt = 0; nt < 8; nt++) {
                Pu[r * 36 + nt * 4 + t] = pack2(s[nt][0], s[nt][1]);
                Pu[(r + 8) * 36 + nt * 4 + t] = pack2(s[nt][2], s[nt][3]);
            }
            __syncwarp();
            // rescale O columns by corr of their q row
            float cq[2][2];
#pragma unroll
            for (int nt = 0; nt < 2; nt++)
#pragma unroll
                for (int j = 0; j < 2; j++)
                    cq[nt][j] = __shfl_sync(0xffffffffu, corr[nt], (2 * t + j) * 4);
#pragma unroll
            for (int mt = 0; mt < 4; mt++)
#pragma unroll
                for (int nt = 0; nt < 2; nt++) {
                    o[mt][nt][0] *= cq[nt][0];
                    o[mt][nt][1] *= cq[nt][1];
                    o[mt][nt][2] *= cq[nt][0];
                    o[mt][nt][3] *= cq[nt][1];
                }
        }

        // O^T += V^T @ P^T  (fp16 mma, 4 k-steps over keys)
#pragma unroll
        for (int kk = 0; kk < 4; kk++) {
            uint32_t bfr[2][2];
#pragma unroll
            for (int nt = 0; nt < 2; nt++) {
                int pr = w * 16 + nt * 8 + g;
                bfr[nt][0] = Pu[pr * 36 + kk * 8 + t];
                bfr[nt][1] = Pu[pr * 36 + kk * 8 + t + 4];
            }
#pragma unroll
            for (int mt = 0; mt < 4; mt++) {
                int r = mt * 16 + g;
                uint32_t a0 = Vu[r * 36 + kk * 8 + t];
                uint32_t a1 = Vu[(r + 8) * 36 + kk * 8 + t];
                uint32_t a2 = Vu[r * 36 + kk * 8 + t + 4];
                uint32_t a3 = Vu[(r + 8) * 36 + kk * 8 + t + 4];
#pragma unroll
                for (int nt = 0; nt < 2; nt++)
                    mma_f16(o[mt][nt], a0, a1, a2, a3, bfr[nt][0], bfr[nt][1]);
            }
        }
    }

    // epilogue: normalize, gate, store fp16 for out-proj
    float inv[2][2];
#pragma unroll
    for (int nt = 0; nt < 2; nt++)
#pragma unroll
        for (int j = 0; j < 2; j++)
            inv[nt][j] = 1.0f / __shfl_sync(0xffffffffu, l_run[nt], (2 * t + j) * 4);

#pragma unroll
    for (int nt = 0; nt < 2; nt++)
#pragma unroll
        for (int j = 0; j < 2; j++) {
            int q = q0 + w * 16 + nt * 8 + 2 * t + j;
            size_t gbase = (((size_t)(b * LL + q)) * HH + h) * 128 + 64;
            size_t obase = (((size_t)(b * LL + q)) * HH + h) * 64;
#pragma unroll
            for (int mt = 0; mt < 4; mt++) {
                int d0 = mt * 16 + g;
                float g0 = d_qg_buf[gbase + d0];
                float g1 = d_qg_buf[gbase + d0 + 8];
                float v0 = o[mt][nt][j] * inv[nt][j] * (1.0f / (1.0f + __expf(-g0)));
                float v1 = o[mt][nt][j + 2] * inv[nt][j] * (1.0f / (1.0f + __expf(-g1)));
                d_ao16[obase + d0]     = __float2half(v0);
                d_ao16[obase + d0 + 8] = __float2half(v1);
            }
        }
}

// ---------------------------------------------------------------------------
extern "C" void kernel_launch(void* const* d_in, const int* in_sizes, int n_in,
                              void* d_out, int out_size)
{
    (void)in_sizes; (void)n_in; (void)out_size;
    const float* h    = (const float*)d_in[0];
    const float* cosb = (const float*)d_in[1];
    const float* sinb = (const float*)d_in[2];
    const float* mask = (const float*)d_in[3];
    const float* wq   = (const float*)d_in[4];
    const float* wk   = (const float*)d_in[5];
    const float* wv   = (const float*)d_in[6];
    const float* wo   = (const float*)d_in[7];
    const float* qnw  = (const float*)d_in[8];
    const float* knw  = (const float*)d_in[9];
    float* out = (float*)d_out;

    float *qg, *kp, *vp;
    __half *h16, *wq16t, *wk16t, *wv16t, *wo16t, *q16, *k16, *vt16, *ao16;
    cudaGetSymbolAddress((void**)&qg, d_qg_buf);
    cudaGetSymbolAddress((void**)&kp, d_k_buf);
    cudaGetSymbolAddress((void**)&vp, d_v_buf);
    cudaGetSymbolAddress((void**)&h16, d_h16);
    cudaGetSymbolAddress((void**)&wq16t, d_wq16t);
    cudaGetSymbolAddress((void**)&wk16t, d_wk16t);
    cudaGetSymbolAddress((void**)&wv16t, d_wv16t);
    cudaGetSymbolAddress((void**)&wo16t, d_wo16t);
    cudaGetSymbolAddress((void**)&q16, d_q16);
    cudaGetSymbolAddress((void**)&k16, d_k16);
    cudaGetSymbolAddress((void**)&vt16, d_vt16);
    cudaGetSymbolAddress((void**)&ao16, d_ao16);

    const int M = BB * LL;   // 8192

    // h -> fp16
    {
        int n8 = (M * EE) / 8;
        cvt_h16_kernel<<<(n8 + 255) / 256, 256>>>((const float4*)h, (uint4*)h16, n8);
    }
    // weights -> transposed fp16 [N][K]
    transpose_w_kernel<<<dim3(2 * HH * DD / 32, EE / 32), dim3(32, 8)>>>(wq, wq16t, EE, 2 * HH * DD);
    transpose_w_kernel<<<dim3(HH * DD / 32, EE / 32), dim3(32, 8)>>>(wk, wk16t, EE, HH * DD);
    transpose_w_kernel<<<dim3(HH * DD / 32, EE / 32), dim3(32, 8)>>>(wv, wv16t, EE, HH * DD);
    transpose_w_kernel<<<dim3(EE / 32, HH * DD / 32), dim3(32, 8)>>>(wo, wo16t, HH * DD, EE);

    cudaFuncSetAttribute(h16_gemm, cudaFuncAttributeMaxDynamicSharedMemorySize,
                         GEMM_SMEM_BYTES);

    // QKV projections (fp16 tensor cores, f32 out)
    h16_gemm<<<dim3(16, 64), 256, GEMM_SMEM_BYTES>>>(h16, wq16t, qg, M, 2 * HH * DD, EE);
    h16_gemm<<<dim3(8, 64), 256, GEMM_SMEM_BYTES>>>(h16, wk16t, kp, M, HH * DD, EE);
    h16_gemm<<<dim3(8, 64), 256, GEMM_SMEM_BYTES>>>(h16, wv16t, vp, M, HH * DD, EE);

    // RMSNorm + partial RoPE -> fp16 q/k
    {
        int warps = BB * LL * HH * 2;
        int blocks = (warps * 32 + 255) / 256;
        norm_rope_kernel<<<blocks, 256>>>(cosb, sinb, qnw, knw);
    }
    // per-head V transpose -> fp16 [b,h,d,l]
    vtrans_kernel<<<dim3(LL / 32, DD / 32, BB * HH), dim3(32, 8)>>>();

    // fused fp16 flash attention + gate
    {
        int smem = ATTN_SMEM_U32 * 4;
        cudaFuncSetAttribute(attn_f16_kernel, cudaFuncAttributeMaxDynamicSharedMemorySize, smem);
        attn_f16_kernel<<<dim3(HH, LL / 128, BB), 256, smem>>>(mask);
    }

    // output projection
    h16_gemm<<<dim3(8, 64), 256, GEMM_SMEM_BYTES>>>(ao16, wo16t, out, M, EE, EE);
}

// round 12
// speedup vs baseline: 1.5322x; 1.0430x over previous
#include <cuda_runtime.h>
#include <cuda_fp16.h>
#include <cstdint>

#define BB 4
#define LL 2048
#define EE 1024
#define HH 16
#define DD 64

// ---------------- scratch ----------------------------------------------------
__device__ float d_qg_buf[(size_t)BB * LL * HH * 2 * DD];  // (b,l,h,2D): q | gate (f32)
__device__ float d_k_buf [(size_t)BB * LL * HH * DD];      // f32 k (pre-norm)
__device__ float d_v_buf [(size_t)BB * LL * HH * DD];      // f32 v
__device__ __half d_h16  [(size_t)BB * LL * EE];           // fp16 h
__device__ __half d_wq16t[(size_t)2 * HH * DD * EE];       // [N][K] fp16
__device__ __half d_wk16t[(size_t)HH * DD * EE];
__device__ __half d_wv16t[(size_t)HH * DD * EE];
__device__ __half d_wo16t[(size_t)EE * HH * DD];
__device__ __half d_q16  [(size_t)BB * LL * HH * DD];      // normed+rope q * 0.125
__device__ __half d_k16  [(size_t)BB * LL * HH * DD];      // normed+rope k
__device__ __half d_vt16 [(size_t)BB * HH * DD * LL];      // V^T per head: [b,h,d,l]
__device__ __half d_ao16 [(size_t)BB * LL * HH * DD];      // gated attn out fp16

// ---------------- helpers ----------------------------------------------------
__device__ __forceinline__ void mma_f16(float* d,
    uint32_t a0, uint32_t a1, uint32_t a2, uint32_t a3,
    uint32_t b0, uint32_t b1)
{
    asm("mma.sync.aligned.m16n8k16.row.col.f32.f16.f16.f32 "
        "{%0,%1,%2,%3}, {%4,%5,%6,%7}, {%8,%9}, {%0,%1,%2,%3};"
        : "+f"(d[0]), "+f"(d[1]), "+f"(d[2]), "+f"(d[3])
        : "r"(a0), "r"(a1), "r"(a2), "r"(a3), "r"(b0), "r"(b1));
}

__device__ __forceinline__ uint32_t smem_u32(const void* p) {
    uint32_t a;
    asm("{ .reg .u64 t; cvta.to.shared.u64 t, %1; cvt.u32.u64 %0, t; }" : "=r"(a) : "l"(p));
    return a;
}

__device__ __forceinline__ uint32_t pack2(float x, float y) {
    __half2 h = __floats2half2_rn(x, y);
    return *(uint32_t*)&h;
}

// ldmatrix: 4x 8x8 b16 matrices; lanes 0-7/8-15/16-23/24-31 give row addrs of
// matrices 0..3, returned in d0..d3.
#define LDSM4(d0, d1, d2, d3, addr) \
    asm volatile("ldmatrix.sync.aligned.m8n8.x4.shared.b16 {%0,%1,%2,%3}, [%4];" \
        : "=r"(d0), "=r"(d1), "=r"(d2), "=r"(d3) : "r"(addr))

#define CP16(dst, src) \
    asm volatile("cp.async.cg.shared.global [%0], [%1], 16;" :: "r"(dst), "l"(src))
#define CP_COMMIT() asm volatile("cp.async.commit_group;")
#define CP_WAIT2()  asm volatile("cp.async.wait_group 2;" ::: "memory")
#define CP_WAIT0()  asm volatile("cp.async.wait_group 0;" ::: "memory")

// ---------------- f32 -> f16 elementwise (8 elems/thread) --------------------
__global__ __launch_bounds__(256) void cvt_h16_kernel(
    const float4* __restrict__ src, uint4* __restrict__ dst, int n8)
{
    int i = blockIdx.x * blockDim.x + threadIdx.x;
    if (i < n8) {
        float4 a = src[2 * i], b = src[2 * i + 1];
        dst[i] = make_uint4(pack2(a.x, a.y), pack2(a.z, a.w),
                            pack2(b.x, b.y), pack2(b.z, b.w));
    }
}

// ---------------- transpose + cvt: W [K][N] f32 -> Wt [N][K] f16 -------------
__global__ __launch_bounds__(256) void transpose_w_kernel(
    const float* __restrict__ in, __half* __restrict__ out, int K, int N)
{
    __shared__ float sm[32][33];
    int n0 = blockIdx.x * 32, k0 = blockIdx.y * 32;
    int tx = threadIdx.x, ty = threadIdx.y;
#pragma unroll
    for (int i = 0; i < 4; i++)
        sm[ty + i * 8][tx] = in[(size_t)(k0 + ty + i * 8) * N + n0 + tx];
    __syncthreads();
#pragma unroll
    for (int i = 0; i < 4; i++)
        out[(size_t)(n0 + ty + i * 8) * K + k0 + tx] = __float2half(sm[tx][ty + i * 8]);
}

// ---------------- per-head V transpose: v[b,l,h,d] f32 -> vt[b,h,d,l] f16 ----
__global__ __launch_bounds__(256) void vtrans_kernel()
{
    __shared__ float sm[32][33];
    int bh = blockIdx.z;                    // b*16 + h
    int b = bh >> 4, h = bh & 15;
    int d0 = blockIdx.y * 32, l0 = blockIdx.x * 32;
    int tx = threadIdx.x, ty = threadIdx.y;
#pragma unroll
    for (int i = 0; i < 4; i++)
        sm[ty + i * 8][tx] =
            d_v_buf[(((size_t)(b * LL + l0 + ty + i * 8)) * HH + h) * DD + d0 + tx];
    __syncthreads();
#pragma unroll
    for (int i = 0; i < 4; i++)
        d_vt16[((size_t)bh * DD + d0 + ty + i * 8) * LL + l0 + tx] =
            __float2half(sm[tx][ty + i * 8]);
}

// ---------------- fp16 GEMM: C[M,N] = A[M,K] @ Bt[N,K]^T ---------------------
// A,Bt fp16 row-major; C f32. 128x128 tile, BK=64, 3-stage cp.async.
// smem u32-stride 36 (=72 f16 = 144B rows). Fragments via ldmatrix.x4.
#define GSTR 36
#define GSTAGE_U32 (2 * 128 * GSTR)              // 9216 u32 = 36864 B
#define GEMM_SMEM_BYTES (3 * GSTAGE_U32 * 4)     // 110592 B

__global__ __launch_bounds__(256, 2) void h16_gemm(
    const __half* __restrict__ A, const __half* __restrict__ Bt,
    float* __restrict__ C, int M, int N, int K)
{
    extern __shared__ uint32_t sh[];
    const uint32_t sbase = smem_u32(sh);

    const int tid = threadIdx.x;
    const int lane = tid & 31;
    const int w = tid >> 5;
    const int t = lane & 3;
    const int wm = w & 3;
    const int wn = w >> 2;
    const int rowBase = blockIdx.y * 128;
    const int colBase = blockIdx.x * 128;

    // ldmatrix lane offsets (bytes) within a [row][144B] tile
    const int q8 = lane >> 3, l8 = lane & 7;
    const uint32_t a_lane = (uint32_t)(((q8 & 1) * 8 + l8) * 144 + (q8 >> 1) * 16);
    const uint32_t b_lane = (uint32_t)(((q8 >> 1) * 8 + l8) * 144 + (q8 & 1) * 16);

    const int crow = tid >> 1;                // 0..127
    const int csb = (tid & 1) * 4;            // seg base (segs of 16B)

    const int nch = K / 64;

    auto issue = [&](int c) {
        if (c < nch) {
            const uint32_t st = sbase + (c % 3) * (GSTAGE_U32 * 4);
            const int k0 = c * 64;
#pragma unroll
            for (int i = 0; i < 4; i++)
                CP16(st + crow * 144 + (csb + i) * 16,
                     &A[(size_t)(rowBase + crow) * K + k0 + (csb + i) * 8]);
            const uint32_t bst = st + 128 * 144;
#pragma unroll
            for (int i = 0; i < 4; i++)
                CP16(bst + crow * 144 + (csb + i) * 16,
                     &Bt[(size_t)(colBase + crow) * K + k0 + (csb + i) * 8]);
        }
        CP_COMMIT();
    };

    float acc[2][8][4];
#pragma unroll
    for (int mt = 0; mt < 2; mt++)
#pragma unroll
        for (int nt = 0; nt < 8; nt++)
#pragma unroll
            for (int j = 0; j < 4; j++) acc[mt][nt][j] = 0.f;

    issue(0); issue(1); issue(2);

    for (int c = 0; c < nch; c++) {
        CP_WAIT2();
        __syncthreads();
        const uint32_t st = sbase + (c % 3) * (GSTAGE_U32 * 4);
        const uint32_t abase = st + (uint32_t)(wm * 32) * 144 + a_lane;
        const uint32_t bbase = st + 128 * 144 + (uint32_t)(wn * 64) * 144 + b_lane;

#pragma unroll
        for (int kk = 0; kk < 4; kk++) {
            const uint32_t kb = kk * 32;
            uint32_t a[2][4];
            LDSM4(a[0][0], a[0][1], a[0][2], a[0][3], abase + kb);
            LDSM4(a[1][0], a[1][1], a[1][2], a[1][3], abase + 16 * 144 + kb);
            uint32_t b[8][2];
#pragma unroll
            for (int p = 0; p < 4; p++)
                LDSM4(b[2 * p][0], b[2 * p][1], b[2 * p + 1][0], b[2 * p + 1][1],
                      bbase + (uint32_t)(p * 16) * 144 + kb);
#pragma unroll
            for (int mt = 0; mt < 2; mt++)
#pragma unroll
                for (int nt = 0; nt < 8; nt++)
                    mma_f16(acc[mt][nt], a[mt][0], a[mt][1], a[mt][2], a[mt][3],
                            b[nt][0], b[nt][1]);
        }
        __syncthreads();
        issue(c + 3);
    }

    const int g = lane >> 2;
#pragma unroll
    for (int mt = 0; mt < 2; mt++) {
        int row = rowBase + wm * 32 + mt * 16 + g;
#pragma unroll
        for (int nt = 0; nt < 8; nt++) {
            int col = colBase + wn * 64 + nt * 8 + 2 * t;
            *(float2*)&C[(size_t)row * N + col] = make_float2(acc[mt][nt][0], acc[mt][nt][1]);
            *(float2*)&C[(size_t)(row + 8) * N + col] = make_float2(acc[mt][nt][2], acc[mt][nt][3]);
        }
    }
}

// ---------------- RMSNorm + partial RoPE -> fp16 q/k -------------------------
__global__ __launch_bounds__(256) void norm_rope_kernel(
    const float* __restrict__ cosb, const float* __restrict__ sinb,
    const float* __restrict__ qw, const float* __restrict__ kw)
{
    int gw = (blockIdx.x * blockDim.x + threadIdx.x) >> 5;
    int lane = threadIdx.x & 31;
    int which = gw & 1;
    int row = gw >> 1;
    if (row >= BB * LL * HH) return;
    int h = row % HH;
    int bl = row / HH;

    const float* ptr;
    const float* w;
    if (which == 0) { ptr = d_qg_buf + ((size_t)bl * HH + h) * (2 * DD); w = qw; }
    else            { ptr = d_k_buf  + ((size_t)bl * HH + h) * DD;       w = kw; }

    float x0 = ptr[lane];
    float x1 = ptr[lane + 32];
    float ss = x0 * x0 + x1 * x1;
#pragma unroll
    for (int o = 16; o; o >>= 1) ss += __shfl_xor_sync(0xffffffffu, ss, o);
    float r = rsqrtf(ss * (1.0f / 64.0f) + 1e-6f);
    x0 = x0 * r * w[lane];
    x1 = x1 * r * w[lane + 32];

    float c0 = 1.f, s0 = 0.f, c1 = 1.f, s1 = 0.f;
    if (lane < 24) {
        const float* cp = cosb + (size_t)bl * DD;
        const float* sp = sinb + (size_t)bl * DD;
        c0 = cp[lane];      s0 = sp[lane];
        c1 = cp[lane + 32]; s1 = sp[lane + 32];
    }
    float r0 = x0 * c0 - x1 * s0;
    float r1 = x1 * c1 + x0 * s1;
    __half* dst;
    if (which == 0) { r0 *= 0.125f; r1 *= 0.125f; dst = d_q16 + ((size_t)bl * HH + h) * DD; }
    else            { dst = d_k16 + ((size_t)bl * HH + h) * DD; }
    dst[lane]      = __float2half(r0);
    dst[lane + 32] = __float2half(r1);
}

// ---------------- fp16 flash attention (register online softmax) + gate ------
// smem (u32): Qu[128*36] Ku[64*36] Vu[64*36] Pu[128*36] Ms(f32)[128*68]
#define AQ_OFF 0
#define AK_OFF (128 * 36)
#define AV_OFF (192 * 36)
#define AP_OFF (256 * 36)
#define AM_OFF (384 * 36)
#define ATTN_SMEM_U32 (384 * 36 + 128 * 68)   // 22528 u32 = 90112 B

__global__ __launch_bounds__(256, 2) void attn_f16_kernel(const float* __restrict__ mask)
{
    extern __shared__ uint32_t sh[];
    uint32_t* Qu = sh + AQ_OFF;
    uint32_t* Ku = sh + AK_OFF;
    uint32_t* Vu = sh + AV_OFF;
    uint32_t* Pu = sh + AP_OFF;
    float* Ms = (float*)(sh + AM_OFF);
    const uint32_t qu_base = smem_u32(Qu);
    const uint32_t ku_base = smem_u32(Ku);
    const uint32_t vu_base = smem_u32(Vu);
    const uint32_t pu_base = smem_u32(Pu);
    const uint32_t ms_base = smem_u32(Ms);

    const int tid = threadIdx.x;
    const int lane = tid & 31;
    const int w = tid >> 5;
    const int g = lane >> 2;
    const int t = lane & 3;
    const int h = blockIdx.x;
    const int q0 = blockIdx.y * 128;
    const int b = blockIdx.z;

    // ldmatrix lane offsets
    const int q8 = lane >> 3, l8 = lane & 7;
    const uint32_t a_lane = (uint32_t)(((q8 & 1) * 8 + l8) * 144 + (q8 >> 1) * 16);
    const uint32_t b_lane = (uint32_t)(((q8 >> 1) * 8 + l8) * 144 + (q8 & 1) * 16);

    // stage Q tile (fp16, pre-scaled): 4 x uint4 per thread
    {
        int row = tid >> 1, sb = (tid & 1) * 4;
#pragma unroll
        for (int i = 0; i < 4; i++) {
            uint4 u = *(const uint4*)&d_q16[(((size_t)(b * LL + q0 + row)) * HH + h) * DD + (sb + i) * 8];
            *(uint4*)&Qu[row * 36 + (sb + i) * 4] = u;
        }
    }

    float o[4][2][4];
#pragma unroll
    for (int mt = 0; mt < 4; mt++)
#pragma unroll
        for (int nt = 0; nt < 2; nt++)
#pragma unroll
            for (int j = 0; j < 4; j++) o[mt][nt][j] = 0.f;

    float m_run[2] = {-1e30f, -1e30f};
    float l_run[2] = {0.f, 0.f};

    const int kvrow = tid >> 2;                 // 0..63
    const int kvsb = (tid & 3) * 2;             // seg base
    const int mrow = tid >> 4;                  // mask row base 0..15
    const int mseg = tid & 15;                  // mask seg 0..15

    // prefetch K / V^T tile 0
    uint4 kr[2], vr[2];
#pragma unroll
    for (int i = 0; i < 2; i++) {
        kr[i] = *(const uint4*)&d_k16[(((size_t)(b * LL + kvrow)) * HH + h) * DD + (kvsb + i) * 8];
        vr[i] = *(const uint4*)&d_vt16[(((size_t)(b * HH + h)) * DD + kvrow) * LL + 0 + (kvsb + i) * 8];
    }

    for (int k0 = 0; k0 < LL; k0 += 64) {
        __syncthreads();
#pragma unroll
        for (int i = 0; i < 2; i++) {
            *(uint4*)&Ku[kvrow * 36 + (kvsb + i) * 4] = kr[i];
            *(uint4*)&Vu[kvrow * 36 + (kvsb + i) * 4] = vr[i];
        }
        if (k0 + 64 < LL) {
#pragma unroll
            for (int i = 0; i < 2; i++) {
                kr[i] = *(const uint4*)&d_k16[(((size_t)(b * LL + k0 + 64 + kvrow)) * HH + h) * DD + (kvsb + i) * 8];
                vr[i] = *(const uint4*)&d_vt16[(((size_t)(b * HH + h)) * DD + kvrow) * LL + k0 + 64 + (kvsb + i) * 8];
            }
        }
        // async mask tile [128 q][64 k] f32 into Ms
#pragma unroll
        for (int i = 0; i < 8; i++) {
            int r = mrow + i * 16;
            CP16(ms_base + r * (68 * 4) + mseg * 16,
                 &mask[((size_t)(b * LL + q0 + r)) * LL + k0 + mseg * 4]);
        }
        CP_COMMIT();
        __syncthreads();

        // S = Q @ K^T  (fp16 mma, 4 k-steps over d) — fragments via ldmatrix
        float s[8][4];
#pragma unroll
        for (int nt = 0; nt < 8; nt++)
#pragma unroll
            for (int j = 0; j < 4; j++) s[nt][j] = 0.f;

        const uint32_t aqb = qu_base + (uint32_t)(w * 16) * 144 + a_lane;
        const uint32_t bkb = ku_base + b_lane;
#pragma unroll
        for (int kk = 0; kk < 4; kk++) {
            const uint32_t kb = kk * 32;
            uint32_t a0, a1, a2, a3;
            LDSM4(a0, a1, a2, a3, aqb + kb);
            uint32_t bfr[8][2];
#pragma unroll
            for (int p = 0; p < 4; p++)
                LDSM4(bfr[2 * p][0], bfr[2 * p][1], bfr[2 * p + 1][0], bfr[2 * p + 1][1],
                      bkb + (uint32_t)(p * 16) * 144 + kb);
#pragma unroll
            for (int nt = 0; nt < 8; nt++)
                mma_f16(s[nt], a0, a1, a2, a3, bfr[nt][0], bfr[nt][1]);
        }

        CP_WAIT0();
        __syncthreads();   // mask visible

        // add mask, online row-max, exp, rowsum, P->fp16
        {
            const float* mp0 = Ms + (w * 16 + g) * 68;
            const float* mp1 = mp0 + 8 * 68;
#pragma unroll
            for (int nt = 0; nt < 8; nt++) {
                float2 m0 = *(const float2*)&mp0[nt * 8 + 2 * t];
                float2 m1 = *(const float2*)&mp1[nt * 8 + 2 * t];
                s[nt][0] += m0.x; s[nt][1] += m0.y;
                s[nt][2] += m1.x; s[nt][3] += m1.y;
            }
            float mx[2] = {-1e30f, -1e30f};
#pragma unroll
            for (int nt = 0; nt < 8; nt++) {
                mx[0] = fmaxf(mx[0], fmaxf(s[nt][0], s[nt][1]));
                mx[1] = fmaxf(mx[1], fmaxf(s[nt][2], s[nt][3]));
            }
#pragma unroll
            for (int i = 0; i < 2; i++) {
                mx[i] = fmaxf(mx[i], __shfl_xor_sync(0xffffffffu, mx[i], 1));
                mx[i] = fmaxf(mx[i], __shfl_xor_sync(0xffffffffu, mx[i], 2));
            }
            float m_new[2], corr[2], sum[2] = {0.f, 0.f};
#pragma unroll
            for (int i = 0; i < 2; i++) {
                m_new[i] = fmaxf(m_run[i], mx[i]);
                corr[i] = __expf(m_run[i] - m_new[i]);
                m_run[i] = m_new[i];
            }
#pragma unroll
            for (int nt = 0; nt < 8; nt++) {
                s[nt][0] = __expf(s[nt][0] - m_new[0]);
                s[nt][1] = __expf(s[nt][1] - m_new[0]);
                s[nt][2] = __expf(s[nt][2] - m_new[1]);
                s[nt][3] = __expf(s[nt][3] - m_new[1]);
                sum[0] += s[nt][0] + s[nt][1];
                sum[1] += s[nt][2] + s[nt][3];
            }
#pragma unroll
            for (int i = 0; i < 2; i++) {
                sum[i] += __shfl_xor_sync(0xffffffffu, sum[i], 1);
                sum[i] += __shfl_xor_sync(0xffffffffu, sum[i], 2);
                l_run[i] = l_run[i] * corr[i] + sum[i];
            }
            // store P fp16 (rows warp-private)
            int r = w * 16 + g;
#pragma unroll
            for (int nt = 0; nt < 8; nt++) {
                Pu[r * 36 + nt * 4 + t] = pack2(s[nt][0], s[nt][1]);
                Pu[(r + 8) * 36 + nt * 4 + t] = pack2(s[nt][2], s[nt][3]);
            }
            __syncwarp();
            // rescale O columns by corr of their q row
            float cq[2][2];
#pragma unroll
            for (int nt = 0; nt < 2; nt++)
#pragma unroll
                for (int j = 0; j < 2; j++)
                    cq[nt][j] = __shfl_sync(0xffffffffu, corr[nt], (2 * t + j) * 4);
#pragma unroll
            for (int mt = 0; mt < 4; mt++)
#pragma unroll
                for (int nt = 0; nt < 2; nt++) {
                    o[mt][nt][0] *= cq[nt][0];
                    o[mt][nt][1] *= cq[nt][1];
                    o[mt][nt][2] *= cq[nt][0];
                    o[mt][nt][3] *= cq[nt][1];
                }
        }

        // O^T += V^T @ P^T  (fragments via ldmatrix)
        const uint32_t avb = vu_base + a_lane;
        const uint32_t bpb = pu_base + (uint32_t)(w * 16) * 144 + b_lane;
#pragma unroll
        for (int kk = 0; kk < 4; kk++) {
            const uint32_t kb = kk * 32;
            uint32_t bfr[2][2];
            LDSM4(bfr[0][0], bfr[0][1], bfr[1][0], bfr[1][1], bpb + kb);
#pragma unroll
            for (int mt = 0; mt < 4; mt++) {
                uint32_t a0, a1, a2, a3;
                LDSM4(a0, a1, a2, a3, avb + (uint32_t)(mt * 16) * 144 + kb);
#pragma unroll
                for (int nt = 0; nt < 2; nt++)
                    mma_f16(o[mt][nt], a0, a1, a2, a3, bfr[nt][0], bfr[nt][1]);
            }
        }
    }

    // epilogue: normalize, gate, store fp16 for out-proj
    float inv[2][2];
#pragma unroll
    for (int nt = 0; nt < 2; nt++)
#pragma unroll
        for (int j = 0; j < 2; j++)
            inv[nt][j] = 1.0f / __shfl_sync(0xffffffffu, l_run[nt], (2 * t + j) * 4);

#pragma unroll
    for (int nt = 0; nt < 2; nt++)
#pragma unroll
        for (int j = 0; j < 2; j++) {
            int q = q0 + w * 16 + nt * 8 + 2 * t + j;
            size_t gbase = (((size_t)(b * LL + q)) * HH + h) * 128 + 64;
            size_t obase = (((size_t)(b * LL + q)) * HH + h) * 64;
#pragma unroll
            for (int mt = 0; mt < 4; mt++) {
                int d0 = mt * 16 + g;
                float g0 = d_qg_buf[gbase + d0];
                float g1 = d_qg_buf[gbase + d0 + 8];
                float v0 = o[mt][nt][j] * inv[nt][j] * (1.0f / (1.0f + __expf(-g0)));
                float v1 = o[mt][nt][j + 2] * inv[nt][j] * (1.0f / (1.0f + __expf(-g1)));
                d_ao16[obase + d0]     = __float2half(v0);
                d_ao16[obase + d0 + 8] = __float2half(v1);
            }
        }
}

// ---------------------------------------------------------------------------
extern "C" void kernel_launch(void* const* d_in, const int* in_sizes, int n_in,
                              void* d_out, int out_size)
{
    (void)in_sizes; (void)n_in; (void)out_size;
    const float* h    = (const float*)d_in[0];
    const float* cosb = (const float*)d_in[1];
    const float* sinb = (const float*)d_in[2];
    const float* mask = (const float*)d_in[3];
    const float* wq   = (const float*)d_in[4];
    const float* wk   = (const float*)d_in[5];
    const float* wv   = (const float*)d_in[6];
    const float* wo   = (const float*)d_in[7];
    const float* qnw  = (const float*)d_in[8];
    const float* knw  = (const float*)d_in[9];
    float* out = (float*)d_out;

    float *qg, *kp, *vp;
    __half *h16, *wq16t, *wk16t, *wv16t, *wo16t, *q16, *k16, *vt16, *ao16;
    cudaGetSymbolAddress((void**)&qg, d_qg_buf);
    cudaGetSymbolAddress((void**)&kp, d_k_buf);
    cudaGetSymbolAddress((void**)&vp, d_v_buf);
    cudaGetSymbolAddress((void**)&h16, d_h16);
    cudaGetSymbolAddress((void**)&wq16t, d_wq16t);
    cudaGetSymbolAddress((void**)&wk16t, d_wk16t);
    cudaGetSymbolAddress((void**)&wv16t, d_wv16t);
    cudaGetSymbolAddress((void**)&wo16t, d_wo16t);
    cudaGetSymbolAddress((void**)&q16, d_q16);
    cudaGetSymbolAddress((void**)&k16, d_k16);
    cudaGetSymbolAddress((void**)&vt16, d_vt16);
    cudaGetSymbolAddress((void**)&ao16, d_ao16);

    const int M = BB * LL;   // 8192

    // h -> fp16
    {
        int n8 = (M * EE) / 8;
        cvt_h16_kernel<<<(n8 + 255) / 256, 256>>>((const float4*)h, (uint4*)h16, n8);
    }
    // weights -> transposed fp16 [N][K]
    transpose_w_kernel<<<dim3(2 * HH * DD / 32, EE / 32), dim3(32, 8)>>>(wq, wq16t, EE, 2 * HH * DD);
    transpose_w_kernel<<<dim3(HH * DD / 32, EE / 32), dim3(32, 8)>>>(wk, wk16t, EE, HH * DD);
    transpose_w_kernel<<<dim3(HH * DD / 32, EE / 32), dim3(32, 8)>>>(wv, wv16t, EE, HH * DD);
    transpose_w_kernel<<<dim3(EE / 32, HH * DD / 32), dim3(32, 8)>>>(wo, wo16t, HH * DD, EE);

    cudaFuncSetAttribute(h16_gemm, cudaFuncAttributeMaxDynamicSharedMemorySize,
                         GEMM_SMEM_BYTES);

    // QKV projections (fp16 tensor cores, f32 out)
    h16_gemm<<<dim3(16, 64), 256, GEMM_SMEM_BYTES>>>(h16, wq16t, qg, M, 2 * HH * DD, EE);
    h16_gemm<<<dim3(8, 64), 256, GEMM_SMEM_BYTES>>>(h16, wk16t, kp, M, HH * DD, EE);
    h16_gemm<<<dim3(8, 64), 256, GEMM_SMEM_BYTES>>>(h16, wv16t, vp, M, HH * DD, EE);

    // RMSNorm + partial RoPE -> fp16 q/k
    {
        int warps = BB * LL * HH * 2;
        int blocks = (warps * 32 + 255) / 256;
        norm_rope_kernel<<<blocks, 256>>>(cosb, sinb, qnw, knw);
    }
    // per-head V transpose -> fp16 [b,h,d,l]
    vtrans_kernel<<<dim3(LL / 32, DD / 32, BB * HH), dim3(32, 8)>>>();

    // fused fp16 flash attention + gate
    {
        int smem = ATTN_SMEM_U32 * 4;
        cudaFuncSetAttribute(attn_f16_kernel, cudaFuncAttributeMaxDynamicSharedMemorySize, smem);
        attn_f16_kernel<<<dim3(HH, LL / 128, BB), 256, smem>>>(mask);
    }

    // output projection
    h16_gemm<<<dim3(8, 64), 256, GEMM_SMEM_BYTES>>>(ao16, wo16t, out, M, EE, EE);
}

// round 14
// speedup vs baseline: 1.5901x; 1.0378x over previous
#include <cuda_runtime.h>
#include <cuda_fp16.h>
#include <cstdint>

#define BB 4
#define LL 2048
#define EE 1024
#define HH 16
#define DD 64
#define NQKV 4096   // merged QKV output columns: 2048 q|gate, 1024 k, 1024 v

// ---------------- scratch ----------------------------------------------------
__device__ float d_qkv_buf[(size_t)BB * LL * NQKV];        // merged f32 QKV out
__device__ __half d_h16   [(size_t)BB * LL * EE];          // fp16 h
__device__ __half d_wqkv16t[(size_t)NQKV * EE];            // [N][K] fp16 (wq|wk|wv)
__device__ __half d_wo16t [(size_t)EE * HH * DD];
__device__ __half d_q16   [(size_t)BB * LL * HH * DD];     // normed+rope q * 0.125
__device__ __half d_k16   [(size_t)BB * LL * HH * DD];     // normed+rope k
__device__ __half d_vt16  [(size_t)BB * HH * DD * LL];     // V^T per head: [b,h,d,l]
__device__ __half d_ao16  [(size_t)BB * LL * HH * DD];     // gated attn out fp16

// ---------------- helpers ----------------------------------------------------
__device__ __forceinline__ void mma_f16(float* d,
    uint32_t a0, uint32_t a1, uint32_t a2, uint32_t a3,
    uint32_t b0, uint32_t b1)
{
    asm("mma.sync.aligned.m16n8k16.row.col.f32.f16.f16.f32 "
        "{%0,%1,%2,%3}, {%4,%5,%6,%7}, {%8,%9}, {%0,%1,%2,%3};"
        : "+f"(d[0]), "+f"(d[1]), "+f"(d[2]), "+f"(d[3])
        : "r"(a0), "r"(a1), "r"(a2), "r"(a3), "r"(b0), "r"(b1));
}

__device__ __forceinline__ uint32_t smem_u32(const void* p) {
    uint32_t a;
    asm("{ .reg .u64 t; cvta.to.shared.u64 t, %1; cvt.u32.u64 %0, t; }" : "=r"(a) : "l"(p));
    return a;
}

__device__ __forceinline__ uint32_t pack2(float x, float y) {
    __half2 h = __floats2half2_rn(x, y);
    return *(uint32_t*)&h;
}

#define LDSM4(d0, d1, d2, d3, addr) \
    asm volatile("ldmatrix.sync.aligned.m8n8.x4.shared.b16 {%0,%1,%2,%3}, [%4];" \
        : "=r"(d0), "=r"(d1), "=r"(d2), "=r"(d3) : "r"(addr))

#define CP16(dst, src) \
    asm volatile("cp.async.cg.shared.global [%0], [%1], 16;" :: "r"(dst), "l"(src))
#define CP_COMMIT() asm volatile("cp.async.commit_group;")
#define CP_WAIT2()  asm volatile("cp.async.wait_group 2;" ::: "memory")
#define CP_WAIT0()  asm volatile("cp.async.wait_group 0;" ::: "memory")

// ---------------- f32 -> f16 elementwise (8 elems/thread) --------------------
__global__ __launch_bounds__(256) void cvt_h16_kernel(
    const float4* __restrict__ src, uint4* __restrict__ dst, int n8)
{
    int i = blockIdx.x * blockDim.x + threadIdx.x;
    if (i < n8) {
        float4 a = src[2 * i], b = src[2 * i + 1];
        dst[i] = make_uint4(pack2(a.x, a.y), pack2(a.z, a.w),
                            pack2(b.x, b.y), pack2(b.z, b.w));
    }
}

// ---------------- transpose + cvt: W [K][N] f32 -> Wt [N][K] f16 -------------
__global__ __launch_bounds__(256) void transpose_w_kernel(
    const float* __restrict__ in, __half* __restrict__ out, int K, int N)
{
    __shared__ float sm[32][33];
    int n0 = blockIdx.x * 32, k0 = blockIdx.y * 32;
    int tx = threadIdx.x, ty = threadIdx.y;
#pragma unroll
    for (int i = 0; i < 4; i++)
        sm[ty + i * 8][tx] = in[(size_t)(k0 + ty + i * 8) * N + n0 + tx];
    __syncthreads();
#pragma unroll
    for (int i = 0; i < 4; i++)
        out[(size_t)(n0 + ty + i * 8) * K + k0 + tx] = __float2half(sm[tx][ty + i * 8]);
}

// ---------------- per-head V transpose: qkv v-cols f32 -> vt[b,h,d,l] f16 ----
__global__ __launch_bounds__(256) void vtrans_kernel()
{
    __shared__ float sm[32][33];
    int bh = blockIdx.z;                    // b*16 + h
    int b = bh >> 4, h = bh & 15;
    int d0 = blockIdx.y * 32, l0 = blockIdx.x * 32;
    int tx = threadIdx.x, ty = threadIdx.y;
#pragma unroll
    for (int i = 0; i < 4; i++)
        sm[ty + i * 8][tx] =
            d_qkv_buf[(size_t)(b * LL + l0 + ty + i * 8) * NQKV + 3072 + h * DD + d0 + tx];
    __syncthreads();
#pragma unroll
    for (int i = 0; i < 4; i++)
        d_vt16[((size_t)bh * DD + d0 + ty + i * 8) * LL + l0 + tx] =
            __float2half(sm[tx][ty + i * 8]);
}

// ---------------- fp16 GEMM: C[M,N] = A[M,K] @ Bt[N,K]^T ---------------------
#define GSTR 36
#define GSTAGE_U32 (2 * 128 * GSTR)              // 9216 u32 = 36864 B
#define GEMM_SMEM_BYTES (3 * GSTAGE_U32 * 4)     // 110592 B

__global__ __launch_bounds__(256, 2) void h16_gemm(
    const __half* __restrict__ A, const __half* __restrict__ Bt,
    float* __restrict__ C, int M, int N, int K)
{
    extern __shared__ uint32_t sh[];
    const uint32_t sbase = smem_u32(sh);

    const int tid = threadIdx.x;
    const int lane = tid & 31;
    const int w = tid >> 5;
    const int t = lane & 3;
    const int wm = w & 3;
    const int wn = w >> 2;
    const int rowBase = blockIdx.y * 128;
    const int colBase = blockIdx.x * 128;

    const int q8 = lane >> 3, l8 = lane & 7;
    const uint32_t a_lane = (uint32_t)(((q8 & 1) * 8 + l8) * 144 + (q8 >> 1) * 16);
    const uint32_t b_lane = (uint32_t)(((q8 >> 1) * 8 + l8) * 144 + (q8 & 1) * 16);

    const int crow = tid >> 1;
    const int csb = (tid & 1) * 4;

    const int nch = K / 64;

    auto issue = [&](int c) {
        if (c < nch) {
            const uint32_t st = sbase + (c % 3) * (GSTAGE_U32 * 4);
            const int k0 = c * 64;
#pragma unroll
            for (int i = 0; i < 4; i++)
                CP16(st + crow * 144 + (csb + i) * 16,
                     &A[(size_t)(rowBase + crow) * K + k0 + (csb + i) * 8]);
            const uint32_t bst = st + 128 * 144;
#pragma unroll
            for (int i = 0; i < 4; i++)
                CP16(bst + crow * 144 + (csb + i) * 16,
                     &Bt[(size_t)(colBase + crow) * K + k0 + (csb + i) * 8]);
        }
        CP_COMMIT();
    };

    float acc[2][8][4];
#pragma unroll
    for (int mt = 0; mt < 2; mt++)
#pragma unroll
        for (int nt = 0; nt < 8; nt++)
#pragma unroll
            for (int j = 0; j < 4; j++) acc[mt][nt][j] = 0.f;

    issue(0); issue(1); issue(2);

    for (int c = 0; c < nch; c++) {
        CP_WAIT2();
        __syncthreads();
        const uint32_t st = sbase + (c % 3) * (GSTAGE_U32 * 4);
        const uint32_t abase = st + (uint32_t)(wm * 32) * 144 + a_lane;
        const uint32_t bbase = st + 128 * 144 + (uint32_t)(wn * 64) * 144 + b_lane;

#pragma unroll
        for (int kk = 0; kk < 4; kk++) {
            const uint32_t kb = kk * 32;
            uint32_t a[2][4];
            LDSM4(a[0][0], a[0][1], a[0][2], a[0][3], abase + kb);
            LDSM4(a[1][0], a[1][1], a[1][2], a[1][3], abase + 16 * 144 + kb);
            uint32_t b[8][2];
#pragma unroll
            for (int p = 0; p < 4; p++)
                LDSM4(b[2 * p][0], b[2 * p][1], b[2 * p + 1][0], b[2 * p + 1][1],
                      bbase + (uint32_t)(p * 16) * 144 + kb);
#pragma unroll
            for (int mt = 0; mt < 2; mt++)
#pragma unroll
                for (int nt = 0; nt < 8; nt++)
                    mma_f16(acc[mt][nt], a[mt][0], a[mt][1], a[mt][2], a[mt][3],
                            b[nt][0], b[nt][1]);
        }
        __syncthreads();
        issue(c + 3);
    }

    const int g = lane >> 2;
#pragma unroll
    for (int mt = 0; mt < 2; mt++) {
        int row = rowBase + wm * 32 + mt * 16 + g;
#pragma unroll
        for (int nt = 0; nt < 8; nt++) {
            int col = colBase + wn * 64 + nt * 8 + 2 * t;
            *(float2*)&C[(size_t)row * N + col] = make_float2(acc[mt][nt][0], acc[mt][nt][1]);
            *(float2*)&C[(size_t)(row + 8) * N + col] = make_float2(acc[mt][nt][2], acc[mt][nt][3]);
        }
    }
}

// ---------------- RMSNorm + partial RoPE -> fp16 q/k -------------------------
__global__ __launch_bounds__(256) void norm_rope_kernel(
    const float* __restrict__ cosb, const float* __restrict__ sinb,
    const float* __restrict__ qw, const float* __restrict__ kw)
{
    int gw = (blockIdx.x * blockDim.x + threadIdx.x) >> 5;
    int lane = threadIdx.x & 31;
    int which = gw & 1;
    int row = gw >> 1;
    if (row >= BB * LL * HH) return;
    int h = row % HH;
    int bl = row / HH;

    const float* ptr;
    const float* w;
    if (which == 0) { ptr = d_qkv_buf + (size_t)bl * NQKV + h * 128;        w = qw; }
    else            { ptr = d_qkv_buf + (size_t)bl * NQKV + 2048 + h * DD;  w = kw; }

    float x0 = ptr[lane];
    float x1 = ptr[lane + 32];
    float ss = x0 * x0 + x1 * x1;
#pragma unroll
    for (int o = 16; o; o >>= 1) ss += __shfl_xor_sync(0xffffffffu, ss, o);
    float r = rsqrtf(ss * (1.0f / 64.0f) + 1e-6f);
    x0 = x0 * r * w[lane];
    x1 = x1 * r * w[lane + 32];

    float c0 = 1.f, s0 = 0.f, c1 = 1.f, s1 = 0.f;
    if (lane < 24) {
        const float* cp = cosb + (size_t)bl * DD;
        const float* sp = sinb + (size_t)bl * DD;
        c0 = cp[lane];      s0 = sp[lane];
        c1 = cp[lane + 32]; s1 = sp[lane + 32];
    }
    float r0 = x0 * c0 - x1 * s0;
    float r1 = x1 * c1 + x0 * s1;
    __half* dst;
    if (which == 0) { r0 *= 0.125f; r1 *= 0.125f; dst = d_q16 + ((size_t)bl * HH + h) * DD; }
    else            { dst = d_k16 + ((size_t)bl * HH + h) * DD; }
    dst[lane]      = __float2half(r0);
    dst[lane + 32] = __float2half(r1);
}

// ---------------- fp16 flash attention, double-buffered K/V ------------------
// smem (u32): Qu[128*36] Ku[2][64*36] Vu[2][64*36] Pu[128*36] Ms(f32)[128*68]
#define AQ_OFF 0
#define AK_OFF (128 * 36)                 // + buf*2304
#define AV_OFF (256 * 36)                 // + buf*2304
#define AP_OFF (384 * 36)
#define AM_OFF (512 * 36)
#define ATTN_SMEM_U32 (512 * 36 + 128 * 68)   // 27136 u32 = 108544 B

__global__ __launch_bounds__(256, 2) void attn_f16_kernel(const float* __restrict__ mask)
{
    extern __shared__ uint32_t sh[];
    uint32_t* Qu = sh + AQ_OFF;
    uint32_t* Pu = sh + AP_OFF;
    float* Ms = (float*)(sh + AM_OFF);
    const uint32_t qu_base = smem_u32(sh) + AQ_OFF * 4;
    const uint32_t ku_base = smem_u32(sh) + AK_OFF * 4;
    const uint32_t vu_base = smem_u32(sh) + AV_OFF * 4;
    const uint32_t pu_base = smem_u32(sh) + AP_OFF * 4;
    const uint32_t ms_base = smem_u32(sh) + AM_OFF * 4;

    const int tid = threadIdx.x;
    const int lane = tid & 31;
    const int w = tid >> 5;
    const int g = lane >> 2;
    const int t = lane & 3;
    const int h = blockIdx.x;
    const int q0 = blockIdx.y * 128;
    const int b = blockIdx.z;

    const int q8 = lane >> 3, l8 = lane & 7;
    const uint32_t a_lane = (uint32_t)(((q8 & 1) * 8 + l8) * 144 + (q8 >> 1) * 16);
    const uint32_t b_lane = (uint32_t)(((q8 >> 1) * 8 + l8) * 144 + (q8 & 1) * 16);

    // stage Q tile (fp16, pre-scaled)
    {
        int row = tid >> 1, sb = (tid & 1) * 4;
#pragma unroll
        for (int i = 0; i < 4; i++) {
            uint4 u = *(const uint4*)&d_q16[(((size_t)(b * LL + q0 + row)) * HH + h) * DD + (sb + i) * 8];
            *(uint4*)&Qu[row * 36 + (sb + i) * 4] = u;
        }
    }

    float o[4][2][4];
#pragma unroll
    for (int mt = 0; mt < 4; mt++)
#pragma unroll
        for (int nt = 0; nt < 2; nt++)
#pragma unroll
            for (int j = 0; j < 4; j++) o[mt][nt][j] = 0.f;

    float m_run[2] = {-1e30f, -1e30f};
    float l_run[2] = {0.f, 0.f};

    const int kvrow = tid >> 2;                 // 0..63
    const int kvsb = (tid & 3) * 2;             // seg base
    const int mrow = tid >> 4;                  // mask row base 0..15
    const int mseg = tid & 15;                  // mask seg 0..15

    // prologue: prefetch tile0, STS into buf0, issue mask0
    uint4 kr[2], vr[2];
#pragma unroll
    for (int i = 0; i < 2; i++) {
        kr[i] = *(const uint4*)&d_k16[(((size_t)(b * LL + kvrow)) * HH + h) * DD + (kvsb + i) * 8];
        vr[i] = *(const uint4*)&d_vt16[(((size_t)(b * HH + h)) * DD + kvrow) * LL + (kvsb + i) * 8];
    }
    {
        uint32_t* Ku0 = sh + AK_OFF;
        uint32_t* Vu0 = sh + AV_OFF;
#pragma unroll
        for (int i = 0; i < 2; i++) {
            *(uint4*)&Ku0[kvrow * 36 + (kvsb + i) * 4] = kr[i];
            *(uint4*)&Vu0[kvrow * 36 + (kvsb + i) * 4] = vr[i];
        }
    }
#pragma unroll
    for (int i = 0; i < 8; i++) {
        int r = mrow + i * 16;
        CP16(ms_base + r * (68 * 4) + mseg * 16,
             &mask[((size_t)(b * LL + q0 + r)) * LL + mseg * 4]);
    }
    CP_COMMIT();
    __syncthreads();

    for (int it = 0; it < LL / 64; it++) {
        const int k0 = it * 64;
        const int cur = it & 1;
        const bool more = (it + 1) < LL / 64;

        // prefetch next K/V tile into regs (overlaps everything below)
        if (more) {
#pragma unroll
            for (int i = 0; i < 2; i++) {
                kr[i] = *(const uint4*)&d_k16[(((size_t)(b * LL + k0 + 64 + kvrow)) * HH + h) * DD + (kvsb + i) * 8];
                vr[i] = *(const uint4*)&d_vt16[(((size_t)(b * HH + h)) * DD + kvrow) * LL + k0 + 64 + (kvsb + i) * 8];
            }
        }

        // S = Q @ K^T from Ku[cur]
        float s[8][4];
#pragma unroll
        for (int nt = 0; nt < 8; nt++)
#pragma unroll
            for (int j = 0; j < 4; j++) s[nt][j] = 0.f;

        const uint32_t aqb = qu_base + (uint32_t)(w * 16) * 144 + a_lane;
        const uint32_t bkb = ku_base + (uint32_t)cur * (2304 * 4) + b_lane;
#pragma unroll
        for (int kk = 0; kk < 4; kk++) {
            const uint32_t kb = kk * 32;
            uint32_t a0, a1, a2, a3;
            LDSM4(a0, a1, a2, a3, aqb + kb);
            uint32_t bfr[8][2];
#pragma unroll
            for (int p = 0; p < 4; p++)
                LDSM4(bfr[2 * p][0], bfr[2 * p][1], bfr[2 * p + 1][0], bfr[2 * p + 1][1],
                      bkb + (uint32_t)(p * 16) * 144 + kb);
#pragma unroll
            for (int nt = 0; nt < 8; nt++)
                mma_f16(s[nt], a0, a1, a2, a3, bfr[nt][0], bfr[nt][1]);
        }

        CP_WAIT0();
        __syncthreads();   // mask tile fully landed (all threads' copies)

        // add mask, online row-max, exp, rowsum, P->fp16
        {
            const float* mp0 = Ms + (w * 16 + g) * 68;
            const float* mp1 = mp0 + 8 * 68;
#pragma unroll
            for (int nt = 0; nt < 8; nt++) {
                float2 m0 = *(const float2*)&mp0[nt * 8 + 2 * t];
                float2 m1 = *(const float2*)&mp1[nt * 8 + 2 * t];
                s[nt][0] += m0.x; s[nt][1] += m0.y;
                s[nt][2] += m1.x; s[nt][3] += m1.y;
            }
            float mx[2] = {-1e30f, -1e30f};
#pragma unroll
            for (int nt = 0; nt < 8; nt++) {
                mx[0] = fmaxf(mx[0], fmaxf(s[nt][0], s[nt][1]));
                mx[1] = fmaxf(mx[1], fmaxf(s[nt][2], s[nt][3]));
            }
#pragma unroll
            for (int i = 0; i < 2; i++) {
                mx[i] = fmaxf(mx[i], __shfl_xor_sync(0xffffffffu, mx[i], 1));
                mx[i] = fmaxf(mx[i], __shfl_xor_sync(0xffffffffu, mx[i], 2));
            }
            float m_new[2], corr[2], sum[2] = {0.f, 0.f};
#pragma unroll
            for (int i = 0; i < 2; i++) {
                m_new[i] = fmaxf(m_run[i], mx[i]);
                corr[i] = __expf(m_run[i] - m_new[i]);
                m_run[i] = m_new[i];
            }
#pragma unroll
            for (int nt = 0; nt < 8; nt++) {
                s[nt][0] = __expf(s[nt][0] - m_new[0]);
                s[nt][1] = __expf(s[nt][1] - m_new[0]);
                s[nt][2] = __expf(s[nt][2] - m_new[1]);
                s[nt][3] = __expf(s[nt][3] - m_new[1]);
                sum[0] += s[nt][0] + s[nt][1];
                sum[1] += s[nt][2] + s[nt][3];
            }
#pragma unroll
            for (int i = 0; i < 2; i++) {
                sum[i] += __shfl_xor_sync(0xffffffffu, sum[i], 1);
                sum[i] += __shfl_xor_sync(0xffffffffu, sum[i], 2);
                l_run[i] = l_run[i] * corr[i] + sum[i];
            }
            int r = w * 16 + g;
#pragma unroll
            for (int nt = 0; nt < 8; nt++) {
                Pu[r * 36 + nt * 4 + t] = pack2(s[nt][0], s[nt][1]);
                Pu[(r + 8) * 36 + nt * 4 + t] = pack2(s[nt][2], s[nt][3]);
            }
            __syncwarp();
            float cq[2][2];
#pragma unroll
            for (int nt = 0; nt < 2; nt++)
#pragma unroll
                for (int j = 0; j < 2; j++)
                    cq[nt][j] = __shfl_sync(0xffffffffu, corr[nt], (2 * t + j) * 4);
#pragma unroll
            for (int mt = 0; mt < 4; mt++)
#pragma unroll
                for (int nt = 0; nt < 2; nt++) {
                    o[mt][nt][0] *= cq[nt][0];
                    o[mt][nt][1] *= cq[nt][1];
                    o[mt][nt][2] *= cq[nt][0];
                    o[mt][nt][3] *= cq[nt][1];
                }
        }

        // O^T += V^T @ P^T from Vu[cur]
        const uint32_t avb = vu_base + (uint32_t)cur * (2304 * 4) + a_lane;
        const uint32_t bpb = pu_base + (uint32_t)(w * 16) * 144 + b_lane;
#pragma unroll
        for (int kk = 0; kk < 4; kk++) {
            const uint32_t kb = kk * 32;
            uint32_t bfr[2][2];
            LDSM4(bfr[0][0], bfr[0][1], bfr[1][0], bfr[1][1], bpb + kb);
#pragma unroll
            for (int mt = 0; mt < 4; mt++) {
                uint32_t a0, a1, a2, a3;
                LDSM4(a0, a1, a2, a3, avb + (uint32_t)(mt * 16) * 144 + kb);
#pragma unroll
                for (int nt = 0; nt < 2; nt++)
                    mma_f16(o[mt][nt], a0, a1, a2, a3, bfr[nt][0], bfr[nt][1]);
            }
        }

        // stage next K/V into the other buffer (overlaps other warps' softmax/PV;
        // safe: buf[cur^1] last read in tile it-1, all warps passed that tile's
        // end barrier before entering this tile)
        if (more) {
            uint32_t* Kn = sh + AK_OFF + (cur ^ 1) * 2304;
            uint32_t* Vn = sh + AV_OFF + (cur ^ 1) * 2304;
#pragma unroll
            for (int i = 0; i < 2; i++) {
                *(uint4*)&Kn[kvrow * 36 + (kvsb + i) * 4] = kr[i];
                *(uint4*)&Vn[kvrow * 36 + (kvsb + i) * 4] = vr[i];
            }
        }
        __syncthreads();   // tile done: next S may read buf[cur^1]; Ms free

        // issue next mask tile (lands under next S-mma)
        if (more) {
#pragma unroll
            for (int i = 0; i < 8; i++) {
                int r = mrow + i * 16;
                CP16(ms_base + r * (68 * 4) + mseg * 16,
                     &mask[((size_t)(b * LL + q0 + r)) * LL + k0 + 64 + mseg * 4]);
            }
            CP_COMMIT();
        }
    }

    // epilogue: normalize, gate, store fp16 for out-proj
    float inv[2][2];
#pragma unroll
    for (int nt = 0; nt < 2; nt++)
#pragma unroll
        for (int j = 0; j < 2; j++)
            inv[nt][j] = 1.0f / __shfl_sync(0xffffffffu, l_run[nt], (2 * t + j) * 4);

#pragma unroll
    for (int nt = 0; nt < 2; nt++)
#pragma unroll
        for (int j = 0; j < 2; j++) {
            int q = q0 + w * 16 + nt * 8 + 2 * t + j;
            size_t gbase = (size_t)(b * LL + q) * NQKV + h * 128 + 64;
            size_t obase = (((size_t)(b * LL + q)) * HH + h) * DD;
#pragma unroll
            for (int mt = 0; mt < 4; mt++) {
                int d0 = mt * 16 + g;
                float g0 = d_qkv_buf[gbase + d0];
                float g1 = d_qkv_buf[gbase + d0 + 8];
                float v0 = o[mt][nt][j] * inv[nt][j] * (1.0f / (1.0f + __expf(-g0)));
                float v1 = o[mt][nt][j + 2] * inv[nt][j] * (1.0f / (1.0f + __expf(-g1)));
                d_ao16[obase + d0]     = __float2half(v0);
                d_ao16[obase + d0 + 8] = __float2half(v1);
            }
        }
}

// ---------------------------------------------------------------------------
extern "C" void kernel_launch(void* const* d_in, const int* in_sizes, int n_in,
                              void* d_out, int out_size)
{
    (void)in_sizes; (void)n_in; (void)out_size;
    const float* h    = (const float*)d_in[0];
    const float* cosb = (const float*)d_in[1];
    const float* sinb = (const float*)d_in[2];
    const float* mask = (const float*)d_in[3];
    const float* wq   = (const float*)d_in[4];
    const float* wk   = (const float*)d_in[5];
    const float* wv   = (const float*)d_in[6];
    const float* wo   = (const float*)d_in[7];
    const float* qnw  = (const float*)d_in[8];
    const float* knw  = (const float*)d_in[9];
    float* out = (float*)d_out;

    float* qkv;
    __half *h16, *wqkv16t, *wo16t, *ao16;
    cudaGetSymbolAddress((void**)&qkv, d_qkv_buf);
    cudaGetSymbolAddress((void**)&h16, d_h16);
    cudaGetSymbolAddress((void**)&wqkv16t, d_wqkv16t);
    cudaGetSymbolAddress((void**)&wo16t, d_wo16t);
    cudaGetSymbolAddress((void**)&ao16, d_ao16);

    const int M = BB * LL;   // 8192

    // h -> fp16
    {
        int n8 = (M * EE) / 8;
        cvt_h16_kernel<<<(n8 + 255) / 256, 256>>>((const float4*)h, (uint4*)h16, n8);
    }
    // weights -> concatenated transposed fp16 [N][K]
    transpose_w_kernel<<<dim3(2 * HH * DD / 32, EE / 32), dim3(32, 8)>>>(
        wq, wqkv16t, EE, 2 * HH * DD);
    transpose_w_kernel<<<dim3(HH * DD / 32, EE / 32), dim3(32, 8)>>>(
        wk, wqkv16t + (size_t)2048 * EE, EE, HH * DD);
    transpose_w_kernel<<<dim3(HH * DD / 32, EE / 32), dim3(32, 8)>>>(
        wv, wqkv16t + (size_t)3072 * EE, EE, HH * DD);
    transpose_w_kernel<<<dim3(EE / 32, HH * DD / 32), dim3(32, 8)>>>(wo, wo16t, HH * DD, EE);

    cudaFuncSetAttribute(h16_gemm, cudaFuncAttributeMaxDynamicSharedMemorySize,
                         GEMM_SMEM_BYTES);

    // merged QKV projection: one launch, N=4096
    h16_gemm<<<dim3(NQKV / 128, M / 128), 256, GEMM_SMEM_BYTES>>>(
        h16, wqkv16t, qkv, M, NQKV, EE);

    // RMSNorm + partial RoPE -> fp16 q/k
    {
        int warps = BB * LL * HH * 2;
        int blocks = (warps * 32 + 255) / 256;
        norm_rope_kernel<<<blocks, 256>>>(cosb, sinb, qnw, knw);
    }
    // per-head V transpose -> fp16 [b,h,d,l]
    vtrans_kernel<<<dim3(LL / 32, DD / 32, BB * HH), dim3(32, 8)>>>();

    // fused fp16 flash attention + gate (double-buffered K/V)
    {
        int smem = ATTN_SMEM_U32 * 4;
        cudaFuncSetAttribute(attn_f16_kernel, cudaFuncAttributeMaxDynamicSharedMemorySize, smem);
        attn_f16_kernel<<<dim3(HH, LL / 128, BB), 256, smem>>>(mask);
    }

    // output projection
    h16_gemm<<<dim3(EE / 128, M / 128), 256, GEMM_SMEM_BYTES>>>(
        ao16, wo16t, out, M, EE, HH * DD);
}